// round 8
// baseline (speedup 1.0000x reference)
#include <cuda_runtime.h>
#include <cuda_fp16.h>
#include <cstdint>
#include <cmath>

#define TQ   4096
#define DM   1024
#define NH   16
#define DH   64
#define KW   (DM / 2)          // k-dim in fp16x2 words = 512

// Scratch (__device__ globals: allocation-free rule)
__device__ __half    g_qkv[(size_t)TQ * 3 * DM];     // [t][3c] fp16, Q pre-scaled (incl log2e)
__device__ uint32_t  g_att[(size_t)TQ * KW];         // attn out, proj-A perm layout
__device__ uint32_t  g_xw[(size_t)TQ * KW];          // x fp16, word-permuted
__device__ uint32_t  g_wqkvT[(size_t)3 * DM * KW];   // w_qkv^T fp16, word-permuted
__device__ uint32_t  g_wprojT[(size_t)DM * KW];      // w_proj^T fp16, word-permuted

// ---------------------------------------------------------------------------
// helpers
// ---------------------------------------------------------------------------
__device__ __forceinline__ uint32_t packh2(float a, float b) {
    __half2 h = __floats2half2_rn(a, b);
    return *reinterpret_cast<uint32_t*>(&h);
}

__device__ __forceinline__ void mma_f16(float* d, const uint32_t* a,
                                        uint32_t b0, uint32_t b1) {
    asm volatile(
        "mma.sync.aligned.m16n8k16.row.col.f32.f16.f16.f32 "
        "{%0,%1,%2,%3}, {%4,%5,%6,%7}, {%8,%9}, {%0,%1,%2,%3};\n"
        : "+f"(d[0]), "+f"(d[1]), "+f"(d[2]), "+f"(d[3])
        : "r"(a[0]), "r"(a[1]), "r"(a[2]), "r"(a[3]), "r"(b0), "r"(b1));
}

__device__ __forceinline__ void ldm_x4(uint32_t* r, uint32_t addr) {
    asm volatile("ldmatrix.sync.aligned.m8n8.x4.shared.b16 {%0,%1,%2,%3}, [%4];"
                 : "=r"(r[0]), "=r"(r[1]), "=r"(r[2]), "=r"(r[3]) : "r"(addr));
}
__device__ __forceinline__ void ldm_x4_t(uint32_t* r, uint32_t addr) {
    asm volatile("ldmatrix.sync.aligned.m8n8.x4.trans.shared.b16 {%0,%1,%2,%3}, [%4];"
                 : "=r"(r[0]), "=r"(r[1]), "=r"(r[2]), "=r"(r[3]) : "r"(addr));
}

__device__ __forceinline__ uint32_t s2u(const void* p) {
    uint32_t a;
    asm("{ .reg .u64 t; cvta.to.shared.u64 t, %1; cvt.u32.u64 %0, t; }"
        : "=r"(a) : "l"(p));
    return a;
}
__device__ __forceinline__ void cpa16(uint32_t dst, const void* src) {
    asm volatile("cp.async.cg.shared.global [%0], [%1], 16;\n" :: "r"(dst), "l"(src));
}
__device__ __forceinline__ void cpa_commit() {
    asm volatile("cp.async.commit_group;\n");
}
template <int N> __device__ __forceinline__ void cpa_wait() {
    asm volatile("cp.async.wait_group %0;\n" :: "n"(N));
}

// ---------------------------------------------------------------------------
// pre-processing: fp32 -> fp16 words, permuted within 8-word (16-elem) groups.
// ---------------------------------------------------------------------------
__global__ void cvt_x_h(const float* __restrict__ in, uint32_t* __restrict__ out,
                        int ngroups)
{
    int gidx = blockIdx.x * blockDim.x + threadIdx.x;
    if (gidx >= ngroups) return;
    const float4* p = (const float4*)(in + (size_t)gidx * 16);
    float f[16];
#pragma unroll
    for (int i = 0; i < 4; i++) {
        float4 v = p[i];
        f[4 * i] = v.x; f[4 * i + 1] = v.y; f[4 * i + 2] = v.z; f[4 * i + 3] = v.w;
    }
    uint32_t w[8];
#pragma unroll
    for (int wp = 0; wp < 8; wp++) {
        int lw = ((wp & 1) << 2) | (wp >> 1);
        w[wp] = packh2(f[2 * lw], f[2 * lw + 1]);
    }
    uint4* o = (uint4*)(out + (size_t)gidx * 8);
    o[0] = make_uint4(w[0], w[1], w[2], w[3]);
    o[1] = make_uint4(w[4], w[5], w[6], w[7]);
}

// in [R][C] fp32 -> out [C][R/2 words] fp16x2, k(=R)-dim word-permuted.
__global__ void wtrans_h(const float* __restrict__ in, uint32_t* __restrict__ out,
                         int R, int C)
{
    __shared__ float t[32][33];
    int c0 = blockIdx.x * 32, r0 = blockIdx.y * 32;
    int tx = threadIdx.x, ty = threadIdx.y;
#pragma unroll
    for (int i = 0; i < 4; i++)
        t[ty + 8 * i][tx] = in[(size_t)(r0 + ty + 8 * i) * C + c0 + tx];
    __syncthreads();
    int Rw = R / 2;
#pragma unroll
    for (int i = 0; i < 2; i++) {
        int wp  = ty + 8 * i;
        int p7  = wp & 7;
        int lwl = (wp & ~7) | (((p7 & 1) << 2) | (p7 >> 1));
        int k0  = 2 * lwl;
        out[(size_t)(c0 + tx) * Rw + r0 / 2 + wp] =
            packh2(t[k0][tx], t[k0 + 1][tx]);
    }
}

// ---------------------------------------------------------------------------
// fp16 GEMM on word-permuted operands: C[M,N] = A[M,K] @ B[N,K]^T
// BM=128, BN=128, stage = 32 words (K=64), 256 thr, 2-stage cp.async.
// MODE 1 (qkv): fp16 output; Q cols (<DM) scaled by 0.125*log2e.
// ---------------------------------------------------------------------------
#define GST 40
#define GSTAGE (2 * 128 * GST)
#define QSCALE (0.125f * 1.4426950408889634f)

template <int MODE>
__global__ __launch_bounds__(256, 2)
void gemm_h(const uint32_t* __restrict__ A, const uint32_t* __restrict__ B,
            void* __restrict__ Cv, int M, int N, int Kw)
{
    __shared__ uint32_t sm[2 * GSTAGE];
    const uint32_t s0 = s2u(sm);

    const int tid  = threadIdx.x;
    const int lane = tid & 31;
    const int warp = tid >> 5;
    const int wm   = warp & 3;
    const int wn   = warp >> 2;
    const int bx   = blockIdx.x;
    const int by   = blockIdx.y;
    const int g    = lane >> 2;
    const int tc   = lane & 3;

    const uint32_t* Ab = A + (size_t)(by * 128) * Kw;
    const uint32_t* Bb = B + (size_t)(bx * 128) * Kw;

    float acc[2][8][4];
#pragma unroll
    for (int mt = 0; mt < 2; mt++)
#pragma unroll
        for (int nt = 0; nt < 8; nt++)
#pragma unroll
            for (int j = 0; j < 4; j++) acc[mt][nt][j] = 0.f;

    auto load_stage = [&](int s, int buf) {
        uint32_t dA = s0 + (uint32_t)(buf * GSTAGE) * 4;
        uint32_t dB = dA + (uint32_t)(128 * GST) * 4;
#pragma unroll
        for (int j = 0; j < 4; j++) {
            int idx = tid + j * 256;
            int r = idx >> 3, c4 = (idx & 7) * 4;
            cpa16(dA + (uint32_t)(r * GST + c4) * 4, Ab + (size_t)r * Kw + s * 32 + c4);
            cpa16(dB + (uint32_t)(r * GST + c4) * 4, Bb + (size_t)r * Kw + s * 32 + c4);
        }
        cpa_commit();
    };

    load_stage(0, 0);
    load_stage(1, 1);

    const int S = Kw / 32;
    for (int s = 0; s < S; s++) {
        if (s + 1 < S) cpa_wait<1>(); else cpa_wait<0>();
        __syncthreads();

        const uint32_t* As = sm + (s & 1) * GSTAGE;
        const uint32_t* Bs = As + 128 * GST;

#pragma unroll
        for (int ks = 0; ks < 4; ks++) {
            int kc = ks * 8 + 2 * tc;
            uint32_t a[2][4];
#pragma unroll
            for (int mt = 0; mt < 2; mt++) {
                int row = wm * 32 + mt * 16 + g;
                uint2 lo = *(const uint2*)(As + row * GST + kc);
                uint2 hi = *(const uint2*)(As + (row + 8) * GST + kc);
                a[mt][0] = lo.x; a[mt][1] = hi.x; a[mt][2] = lo.y; a[mt][3] = hi.y;
            }
#pragma unroll
            for (int nt = 0; nt < 8; nt++) {
                int nr = wn * 64 + nt * 8 + g;
                uint2 b = *(const uint2*)(Bs + nr * GST + kc);
                mma_f16(acc[0][nt], a[0], b.x, b.y);
                mma_f16(acc[1][nt], a[1], b.x, b.y);
            }
        }
        __syncthreads();
        if (s + 2 < S) load_stage(s + 2, s & 1);
    }

    // epilogue
#pragma unroll
    for (int mt = 0; mt < 2; mt++)
#pragma unroll
        for (int nt = 0; nt < 8; nt++) {
            int r0 = by * 128 + wm * 32 + mt * 16 + g;
            int c0 = bx * 128 + wn * 64 + nt * 8 + 2 * tc;
            float v0 = acc[mt][nt][0], v1 = acc[mt][nt][1];
            float v2 = acc[mt][nt][2], v3 = acc[mt][nt][3];
            if (MODE == 1) {
                float sc = (c0 < DM) ? QSCALE : 1.0f;   // Q: fold 1/8 and log2e
                uint32_t* C = (uint32_t*)Cv;
                int cw = c0 >> 1;
                C[(size_t)r0 * (N / 2) + cw]       = packh2(v0 * sc, v1 * sc);
                C[(size_t)(r0 + 8) * (N / 2) + cw] = packh2(v2 * sc, v3 * sc);
            } else {
                float* C = (float*)Cv;
                *(float2*)(C + (size_t)r0 * N + c0)       = make_float2(v0, v1);
                *(float2*)(C + (size_t)(r0 + 8) * N + c0) = make_float2(v2, v3);
            }
        }
}

// ---------------------------------------------------------------------------
// Causal flash attention, fp16 mma m16n8k16.
// 128 q-rows per CTA (8 warps x 16), kv tiles of 64. Scores are in log2
// units (Q pre-scaled by 0.125*log2e) -> softmax uses exp2f.
// smem 36.9 KB static -> 2 CTAs/SM (16 warps).
// ---------------------------------------------------------------------------
#define RW 36
__global__ __launch_bounds__(256) void attn_fwd()
{
    __shared__ __align__(16) uint32_t smQ[128 * RW];
    __shared__ __align__(16) uint32_t smK[64 * RW];
    __shared__ __align__(16) uint32_t smV[64 * RW];
    const uint32_t bQ = s2u(smQ), bK = s2u(smK), bV = s2u(smV);

    const int tid  = threadIdx.x;
    const int lane = tid & 31;
    const int warp = tid >> 5;
    const int h    = blockIdx.y;
    const int qi   = (int)gridDim.x - 1 - (int)blockIdx.x;  // heavy tiles first
    const int q0   = qi * 128;
    const int g    = lane >> 2;
    const int tc   = lane & 3;

    // ---- prologue: Q tile (128 x 64 fp16 = 1024 x 16B over 256 thr) ----
#pragma unroll
    for (int i = 0; i < 4; i++) {
        int idx = tid + i * 256;
        int r = idx >> 3, ch = idx & 7;
        cpa16(bQ + (uint32_t)(r * RW + ch * 4) * 4,
              g_qkv + (size_t)(q0 + r) * (3 * DM) + h * DH + ch * 8);
    }
    cpa_commit();

    // ldmatrix base offsets
    const uint32_t qoff = (uint32_t)((warp * 16 + (lane & 15)) * RW +
                                     ((lane >> 4) << 2)) * 4;
    const uint32_t koff = (uint32_t)(((lane & 7) + ((lane >> 4) << 3)) * RW +
                                     (((lane >> 3) & 1) << 2)) * 4;
    const uint32_t voff = (uint32_t)((lane & 15) * RW + ((lane >> 4) << 2)) * 4;

    float o[8][4];
#pragma unroll
    for (int nt = 0; nt < 8; nt++)
#pragma unroll
        for (int j = 0; j < 4; j++) o[nt][j] = 0.f;
    float mA = -INFINITY, mB = -INFINITY, lA = 0.f, lB = 0.f;

    const int nt_tiles = 2 * qi + 2;

    for (int t = 0; t < nt_tiles; t++) {
        __syncthreads();           // prior tile's PV done with K/V buffers
#pragma unroll
        for (int i = 0; i < 2; i++) {
            int idx = tid + i * 256;
            int r = idx >> 3, ch = idx & 7;
            const __half* base = g_qkv + (size_t)(t * 64 + r) * (3 * DM) + h * DH + ch * 8;
            cpa16(bK + (uint32_t)(r * RW + ch * 4) * 4, base + DM);
            cpa16(bV + (uint32_t)(r * RW + ch * 4) * 4, base + 2 * DM);
        }
        cpa_commit();
        cpa_wait<0>();
        __syncthreads();

        // ---- S = Q @ K^T : warp computes 16 x 64 (scores in log2 units) ----
        float s[8][4];
#pragma unroll
        for (int nt = 0; nt < 8; nt++)
#pragma unroll
            for (int j = 0; j < 4; j++) s[nt][j] = 0.f;

#pragma unroll
        for (int kc = 0; kc < 4; kc++) {
            uint32_t a[4];
            ldm_x4(a, bQ + qoff + (uint32_t)(8 * kc) * 4);
#pragma unroll
            for (int ntp = 0; ntp < 4; ntp++) {
                uint32_t b[4];
                ldm_x4(b, bK + koff + (uint32_t)(ntp * 16 * RW + 8 * kc) * 4);
                mma_f16(s[2 * ntp],     a, b[0], b[1]);
                mma_f16(s[2 * ntp + 1], a, b[2], b[3]);
            }
        }

        // ---- causal mask (last two kv tiles clip) ----
        if (t >= 2 * qi) {
            int qlA = q0 + warp * 16 + g;
            int qlB = qlA + 8;
#pragma unroll
            for (int nt = 0; nt < 8; nt++) {
                int k0 = t * 64 + nt * 8 + 2 * tc;
                if (k0     > qlA) s[nt][0] = -INFINITY;
                if (k0 + 1 > qlA) s[nt][1] = -INFINITY;
                if (k0     > qlB) s[nt][2] = -INFINITY;
                if (k0 + 1 > qlB) s[nt][3] = -INFINITY;
            }
        }

        // ---- online softmax (base-2) ----
        float rA = -INFINITY, rB = -INFINITY;
#pragma unroll
        for (int nt = 0; nt < 8; nt++) {
            rA = fmaxf(rA, fmaxf(s[nt][0], s[nt][1]));
            rB = fmaxf(rB, fmaxf(s[nt][2], s[nt][3]));
        }
        rA = fmaxf(rA, __shfl_xor_sync(0xffffffffu, rA, 1));
        rA = fmaxf(rA, __shfl_xor_sync(0xffffffffu, rA, 2));
        rB = fmaxf(rB, __shfl_xor_sync(0xffffffffu, rB, 1));
        rB = fmaxf(rB, __shfl_xor_sync(0xffffffffu, rB, 2));

        float mAn = fmaxf(mA, rA), mBn = fmaxf(mB, rB);
        float fA = exp2f(mA - mAn), fB = exp2f(mB - mBn);

        float sumA = 0.f, sumB = 0.f;
#pragma unroll
        for (int nt = 0; nt < 8; nt++) {
            s[nt][0] = exp2f(s[nt][0] - mAn);
            s[nt][1] = exp2f(s[nt][1] - mAn);
            s[nt][2] = exp2f(s[nt][2] - mBn);
            s[nt][3] = exp2f(s[nt][3] - mBn);
            sumA += s[nt][0] + s[nt][1];
            sumB += s[nt][2] + s[nt][3];
        }
        sumA += __shfl_xor_sync(0xffffffffu, sumA, 1);
        sumA += __shfl_xor_sync(0xffffffffu, sumA, 2);
        sumB += __shfl_xor_sync(0xffffffffu, sumB, 1);
        sumB += __shfl_xor_sync(0xffffffffu, sumB, 2);

        lA = lA * fA + sumA;
        lB = lB * fB + sumB;
        mA = mAn; mB = mBn;
#pragma unroll
        for (int nt = 0; nt < 8; nt++) {
            o[nt][0] *= fA; o[nt][1] *= fA;
            o[nt][2] *= fB; o[nt][3] *= fB;
        }

        // ---- O += P @ V  (P from registers; V via ldmatrix.trans) ----
#pragma unroll
        for (int kc = 0; kc < 4; kc++) {
            uint32_t pa[4];
            pa[0] = packh2(s[2 * kc][0],     s[2 * kc][1]);
            pa[1] = packh2(s[2 * kc][2],     s[2 * kc][3]);
            pa[2] = packh2(s[2 * kc + 1][0], s[2 * kc + 1][1]);
            pa[3] = packh2(s[2 * kc + 1][2], s[2 * kc + 1][3]);
#pragma unroll
            for (int ntp = 0; ntp < 4; ntp++) {
                uint32_t b[4];
                ldm_x4_t(b, bV + voff + (uint32_t)(16 * kc * RW + ntp * 8) * 4);
                mma_f16(o[2 * ntp],     pa, b[0], b[1]);
                mma_f16(o[2 * ntp + 1], pa, b[2], b[3]);
            }
        }
    }

    // ---- epilogue: normalize, emit proj-A (word-permuted fp16) layout ----
    float invA = 1.f / lA, invB = 1.f / lB;
    int rowA = q0 + warp * 16 + g;
#pragma unroll
    for (int nt = 0; nt < 8; nt++) {
        int hw   = h * 32 + nt * 4 + tc;
        int phys = (hw & ~7) | (2 * (hw & 3) + ((hw & 7) >> 2));
        g_att[(size_t)rowA * KW + phys]       = packh2(o[nt][0] * invA, o[nt][1] * invA);
        g_att[(size_t)(rowA + 8) * KW + phys] = packh2(o[nt][2] * invB, o[nt][3] * invB);
    }
}

// ---------------------------------------------------------------------------
// Launch
// ---------------------------------------------------------------------------
extern "C" void kernel_launch(void* const* d_in, const int* in_sizes, int n_in,
                              void* d_out, int out_size)
{
    const float* x      = (const float*)d_in[0];
    const float* w_qkv  = (const float*)d_in[1];
    const float* w_proj = (const float*)d_in[2];
    float* out          = (float*)d_out;

    void *qkv_p, *att_p, *xw_p, *wqkvT_p, *wprojT_p;
    cudaGetSymbolAddress(&qkv_p,    g_qkv);
    cudaGetSymbolAddress(&att_p,    g_att);
    cudaGetSymbolAddress(&xw_p,     g_xw);
    cudaGetSymbolAddress(&wqkvT_p,  g_wqkvT);
    cudaGetSymbolAddress(&wprojT_p, g_wprojT);

    // 0) pre-process
    cvt_x_h<<<(TQ * DM / 16 + 255) / 256, 256>>>(x, (uint32_t*)xw_p, TQ * DM / 16);
    wtrans_h<<<dim3(3 * DM / 32, DM / 32), dim3(32, 8)>>>(w_qkv, (uint32_t*)wqkvT_p,
                                                          DM, 3 * DM);
    wtrans_h<<<dim3(DM / 32, DM / 32), dim3(32, 8)>>>(w_proj, (uint32_t*)wprojT_p,
                                                      DM, DM);

    // 1) QKV projection
    gemm_h<1><<<dim3(3 * DM / 128, TQ / 128), 256>>>(
        (const uint32_t*)xw_p, (const uint32_t*)wqkvT_p, qkv_p, TQ, 3 * DM, KW);

    // 2) causal attention (128 q-rows/CTA, 8 warps)
    attn_fwd<<<dim3(TQ / 128, NH), 256>>>();

    // 3) output projection
    gemm_h<0><<<dim3(DM / 128, TQ / 128), 256>>>(
        (const uint32_t*)att_p, (const uint32_t*)wprojT_p, out, TQ, DM, KW);
}

// round 9
// speedup vs baseline: 1.0743x; 1.0743x over previous
#include <cuda_runtime.h>
#include <cuda_fp16.h>
#include <cstdint>
#include <cmath>

#define TQ   4096
#define DM   1024
#define NH   16
#define DH   64
#define KW   (DM / 2)          // k-dim in fp16x2 words = 512

// Scratch (__device__ globals: allocation-free rule)
__device__ __half    g_qkv[(size_t)TQ * 3 * DM];     // [t][3c] fp16, Q pre-scaled (incl log2e)
__device__ uint32_t  g_att[(size_t)TQ * KW];         // attn out fp16 words (canonical)
__device__ uint32_t  g_xw[(size_t)TQ * KW];          // x fp16 words
__device__ uint32_t  g_wqkvT[(size_t)3 * DM * KW];   // w_qkv^T fp16 words [3DM][KW]
__device__ uint32_t  g_wprojT[(size_t)DM * KW];      // w_proj^T fp16 words [DM][KW]

// ---------------------------------------------------------------------------
// helpers
// ---------------------------------------------------------------------------
__device__ __forceinline__ uint32_t packh2(float a, float b) {
    __half2 h = __floats2half2_rn(a, b);
    return *reinterpret_cast<uint32_t*>(&h);
}

__device__ __forceinline__ void mma_f16(float* d, const uint32_t* a,
                                        uint32_t b0, uint32_t b1) {
    asm volatile(
        "mma.sync.aligned.m16n8k16.row.col.f32.f16.f16.f32 "
        "{%0,%1,%2,%3}, {%4,%5,%6,%7}, {%8,%9}, {%0,%1,%2,%3};\n"
        : "+f"(d[0]), "+f"(d[1]), "+f"(d[2]), "+f"(d[3])
        : "r"(a[0]), "r"(a[1]), "r"(a[2]), "r"(a[3]), "r"(b0), "r"(b1));
}

__device__ __forceinline__ void ldm_x4(uint32_t* r, uint32_t addr) {
    asm volatile("ldmatrix.sync.aligned.m8n8.x4.shared.b16 {%0,%1,%2,%3}, [%4];"
                 : "=r"(r[0]), "=r"(r[1]), "=r"(r[2]), "=r"(r[3]) : "r"(addr));
}
__device__ __forceinline__ void ldm_x4_t(uint32_t* r, uint32_t addr) {
    asm volatile("ldmatrix.sync.aligned.m8n8.x4.trans.shared.b16 {%0,%1,%2,%3}, [%4];"
                 : "=r"(r[0]), "=r"(r[1]), "=r"(r[2]), "=r"(r[3]) : "r"(addr));
}

__device__ __forceinline__ uint32_t s2u(const void* p) {
    uint32_t a;
    asm("{ .reg .u64 t; cvta.to.shared.u64 t, %1; cvt.u32.u64 %0, t; }"
        : "=r"(a) : "l"(p));
    return a;
}
__device__ __forceinline__ void cpa16(uint32_t dst, const void* src) {
    asm volatile("cp.async.cg.shared.global [%0], [%1], 16;\n" :: "r"(dst), "l"(src));
}
__device__ __forceinline__ void cpa_commit() {
    asm volatile("cp.async.commit_group;\n");
}
template <int N> __device__ __forceinline__ void cpa_wait() {
    asm volatile("cp.async.wait_group %0;\n" :: "n"(N));
}

// ---------------------------------------------------------------------------
// pre-processing (canonical layouts, no permutation)
// ---------------------------------------------------------------------------
__global__ void cvt_h(const float* __restrict__ in, uint32_t* __restrict__ out,
                      int nwords)   // nwords = n_floats/2
{
    int i = blockIdx.x * blockDim.x + threadIdx.x;   // word-quad index
    if (i * 4 >= nwords) return;
    const float4* p = (const float4*)(in + (size_t)i * 8);
    float4 v0 = p[0], v1 = p[1];
    uint4 w;
    w.x = packh2(v0.x, v0.y);
    w.y = packh2(v0.z, v0.w);
    w.z = packh2(v1.x, v1.y);
    w.w = packh2(v1.z, v1.w);
    *(uint4*)(out + (size_t)i * 4) = w;
}

// in [R][C] fp32 -> out [C][R/2 words] fp16x2 (canonical).
__global__ void wtrans_h(const float* __restrict__ in, uint32_t* __restrict__ out,
                         int R, int C)
{
    __shared__ float t[32][33];
    int c0 = blockIdx.x * 32, r0 = blockIdx.y * 32;
    int tx = threadIdx.x, ty = threadIdx.y;
#pragma unroll
    for (int i = 0; i < 4; i++)
        t[ty + 8 * i][tx] = in[(size_t)(r0 + ty + 8 * i) * C + c0 + tx];
    __syncthreads();
    int Rw = R / 2;
#pragma unroll
    for (int i = 0; i < 2; i++) {
        int wp = ty + 8 * i;                 // local word 0..15
        out[(size_t)(c0 + tx) * Rw + r0 / 2 + wp] =
            packh2(t[2 * wp][tx], t[2 * wp + 1][tx]);
    }
}

// ---------------------------------------------------------------------------
// fp16 GEMM, ldmatrix fragments: C[M,N] = A[M,K] @ B[N,K]^T
// BM=128, BN=128, stage = 32 words (K=64), 256 thr (4 warps M x 2 warps N,
// warp tile 32x64), 2-stage cp.async double buffer.
// MODE 1 (qkv): fp16 word output; Q cols (<DM) scaled by 0.125*log2e.
// ---------------------------------------------------------------------------
#define GST 36                       // smem row stride in words
#define GOPER (128 * GST)            // words per operand per stage
#define GSTAGE (2 * GOPER)           // words per stage (A then B)
#define QSCALE (0.125f * 1.4426950408889634f)

template <int MODE>
__global__ __launch_bounds__(256, 2)
void gemm_h(const uint32_t* __restrict__ A, const uint32_t* __restrict__ B,
            void* __restrict__ Cv, int M, int N, int Kw)
{
    __shared__ __align__(16) uint32_t sm[2 * GSTAGE];
    const uint32_t s0 = s2u(sm);

    const int tid  = threadIdx.x;
    const int lane = tid & 31;
    const int warp = tid >> 5;
    const int wm   = warp & 3;
    const int wn   = warp >> 2;
    const int bx   = blockIdx.x;
    const int by   = blockIdx.y;
    const int g    = lane >> 2;
    const int tc   = lane & 3;

    const uint32_t* Ab = A + (size_t)(by * 128) * Kw;
    const uint32_t* Bb = B + (size_t)(bx * 128) * Kw;

    float acc[2][8][4];
#pragma unroll
    for (int mt = 0; mt < 2; mt++)
#pragma unroll
        for (int nt = 0; nt < 8; nt++)
#pragma unroll
            for (int j = 0; j < 4; j++) acc[mt][nt][j] = 0.f;

    auto load_stage = [&](int s, int buf) {
        uint32_t dA = s0 + (uint32_t)(buf * GSTAGE) * 4;
        uint32_t dB = dA + (uint32_t)GOPER * 4;
#pragma unroll
        for (int j = 0; j < 4; j++) {
            int idx = tid + j * 256;
            int r = idx >> 3, c4 = (idx & 7) * 4;
            cpa16(dA + (uint32_t)(r * GST + c4) * 4, Ab + (size_t)r * Kw + s * 32 + c4);
            cpa16(dB + (uint32_t)(r * GST + c4) * 4, Bb + (size_t)r * Kw + s * 32 + c4);
        }
        cpa_commit();
    };

    load_stage(0, 0);
    load_stage(1, 1);

    // ldmatrix per-thread base offsets (bytes)
    const uint32_t aoff = (uint32_t)((wm * 32 + (lane & 15)) * GST +
                                     ((lane >> 4) << 2)) * 4;
    const uint32_t boff = (uint32_t)((wn * 64 + (lane & 7) + ((lane >> 4) << 3)) * GST +
                                     (((lane >> 3) & 1) << 2)) * 4;

    const int S = Kw / 32;
    for (int s = 0; s < S; s++) {
        if (s + 1 < S) cpa_wait<1>(); else cpa_wait<0>();
        __syncthreads();

        const uint32_t bA = s0 + (uint32_t)((s & 1) * GSTAGE) * 4;
        const uint32_t bB = bA + (uint32_t)GOPER * 4;

#pragma unroll
        for (int ks = 0; ks < 4; ks++) {
            uint32_t a[2][4];
            ldm_x4(a[0], bA + aoff + (uint32_t)(ks * 8) * 4);
            ldm_x4(a[1], bA + aoff + (uint32_t)(16 * GST + ks * 8) * 4);
#pragma unroll
            for (int nt2 = 0; nt2 < 4; nt2++) {
                uint32_t b[4];
                ldm_x4(b, bB + boff + (uint32_t)(nt2 * 16 * GST + ks * 8) * 4);
                mma_f16(acc[0][2 * nt2],     a[0], b[0], b[1]);
                mma_f16(acc[1][2 * nt2],     a[1], b[0], b[1]);
                mma_f16(acc[0][2 * nt2 + 1], a[0], b[2], b[3]);
                mma_f16(acc[1][2 * nt2 + 1], a[1], b[2], b[3]);
            }
        }
        __syncthreads();
        if (s + 2 < S) load_stage(s + 2, s & 1);
    }

    // epilogue
#pragma unroll
    for (int mt = 0; mt < 2; mt++)
#pragma unroll
        for (int nt = 0; nt < 8; nt++) {
            int r0 = by * 128 + wm * 32 + mt * 16 + g;
            int c0 = bx * 128 + wn * 64 + nt * 8 + 2 * tc;
            float v0 = acc[mt][nt][0], v1 = acc[mt][nt][1];
            float v2 = acc[mt][nt][2], v3 = acc[mt][nt][3];
            if (MODE == 1) {
                float sc = (c0 < DM) ? QSCALE : 1.0f;   // Q: fold 1/8 and log2e
                uint32_t* C = (uint32_t*)Cv;
                int cw = c0 >> 1;
                C[(size_t)r0 * (N / 2) + cw]       = packh2(v0 * sc, v1 * sc);
                C[(size_t)(r0 + 8) * (N / 2) + cw] = packh2(v2 * sc, v3 * sc);
            } else {
                float* C = (float*)Cv;
                *(float2*)(C + (size_t)r0 * N + c0)       = make_float2(v0, v1);
                *(float2*)(C + (size_t)(r0 + 8) * N + c0) = make_float2(v2, v3);
            }
        }
}

// ---------------------------------------------------------------------------
// Causal flash attention, fp16 mma m16n8k16. 64 q-rows, 4 warps (proven
// best shape). Scores in log2 units -> exp2f softmax. P passes S->PV in
// registers; V via ldmatrix.trans. smem 27.6 KB.
// ---------------------------------------------------------------------------
#define RW 36
__global__ __launch_bounds__(128) void attn_fwd()
{
    __shared__ __align__(16) uint32_t smQ[64 * RW];
    __shared__ __align__(16) uint32_t smK[64 * RW];
    __shared__ __align__(16) uint32_t smV[64 * RW];
    const uint32_t bQ = s2u(smQ), bK = s2u(smK), bV = s2u(smV);

    const int tid  = threadIdx.x;
    const int lane = tid & 31;
    const int warp = tid >> 5;
    const int h    = blockIdx.y;
    const int qt   = (int)gridDim.x - 1 - (int)blockIdx.x;  // heavy tiles first
    const int q0   = qt * 64;
    const int g    = lane >> 2;
    const int tc   = lane & 3;

    // ---- prologue: Q tile (64 x 64 fp16 = 512 x 16B) ----
#pragma unroll
    for (int i = 0; i < 4; i++) {
        int idx = tid + i * 128;
        int r = idx >> 3, ch = idx & 7;
        cpa16(bQ + (uint32_t)(r * RW + ch * 4) * 4,
              g_qkv + (size_t)(q0 + r) * (3 * DM) + h * DH + ch * 8);
    }
    cpa_commit();

    // ldmatrix base offsets
    const uint32_t qoff = (uint32_t)((warp * 16 + (lane & 15)) * RW +
                                     ((lane >> 4) << 2)) * 4;
    const uint32_t koff = (uint32_t)(((lane & 7) + ((lane >> 4) << 3)) * RW +
                                     (((lane >> 3) & 1) << 2)) * 4;
    const uint32_t voff = (uint32_t)((lane & 15) * RW + ((lane >> 4) << 2)) * 4;

    float o[8][4];
#pragma unroll
    for (int nt = 0; nt < 8; nt++)
#pragma unroll
        for (int j = 0; j < 4; j++) o[nt][j] = 0.f;
    float mA = -INFINITY, mB = -INFINITY, lA = 0.f, lB = 0.f;

    for (int t = 0; t <= qt; t++) {
        __syncthreads();           // prior tile's PV done with K/V buffers
#pragma unroll
        for (int i = 0; i < 4; i++) {
            int idx = tid + i * 128;
            int r = idx >> 3, ch = idx & 7;
            const __half* base = g_qkv + (size_t)(t * 64 + r) * (3 * DM) + h * DH + ch * 8;
            cpa16(bK + (uint32_t)(r * RW + ch * 4) * 4, base + DM);
            cpa16(bV + (uint32_t)(r * RW + ch * 4) * 4, base + 2 * DM);
        }
        cpa_commit();
        cpa_wait<0>();
        __syncthreads();

        // ---- S = Q @ K^T : warp computes 16 x 64 (log2-unit scores) ----
        float s[8][4];
#pragma unroll
        for (int nt = 0; nt < 8; nt++)
#pragma unroll
            for (int j = 0; j < 4; j++) s[nt][j] = 0.f;

#pragma unroll
        for (int kc = 0; kc < 4; kc++) {
            uint32_t a[4];
            ldm_x4(a, bQ + qoff + (uint32_t)(8 * kc) * 4);
#pragma unroll
            for (int ntp = 0; ntp < 4; ntp++) {
                uint32_t b[4];
                ldm_x4(b, bK + koff + (uint32_t)(ntp * 16 * RW + 8 * kc) * 4);
                mma_f16(s[2 * ntp],     a, b[0], b[1]);
                mma_f16(s[2 * ntp + 1], a, b[2], b[3]);
            }
        }

        // ---- causal mask on diagonal tile ----
        if (t == qt) {
            int qlA = warp * 16 + g;
            int qlB = qlA + 8;
#pragma unroll
            for (int nt = 0; nt < 8; nt++) {
                int k0 = nt * 8 + 2 * tc;
                if (k0     > qlA) s[nt][0] = -INFINITY;
                if (k0 + 1 > qlA) s[nt][1] = -INFINITY;
                if (k0     > qlB) s[nt][2] = -INFINITY;
                if (k0 + 1 > qlB) s[nt][3] = -INFINITY;
            }
        }

        // ---- online softmax (base-2) ----
        float rA = -INFINITY, rB = -INFINITY;
#pragma unroll
        for (int nt = 0; nt < 8; nt++) {
            rA = fmaxf(rA, fmaxf(s[nt][0], s[nt][1]));
            rB = fmaxf(rB, fmaxf(s[nt][2], s[nt][3]));
        }
        rA = fmaxf(rA, __shfl_xor_sync(0xffffffffu, rA, 1));
        rA = fmaxf(rA, __shfl_xor_sync(0xffffffffu, rA, 2));
        rB = fmaxf(rB, __shfl_xor_sync(0xffffffffu, rB, 1));
        rB = fmaxf(rB, __shfl_xor_sync(0xffffffffu, rB, 2));

        float mAn = fmaxf(mA, rA), mBn = fmaxf(mB, rB);
        float fA = exp2f(mA - mAn), fB = exp2f(mB - mBn);

        float sumA = 0.f, sumB = 0.f;
#pragma unroll
        for (int nt = 0; nt < 8; nt++) {
            s[nt][0] = exp2f(s[nt][0] - mAn);
            s[nt][1] = exp2f(s[nt][1] - mAn);
            s[nt][2] = exp2f(s[nt][2] - mBn);
            s[nt][3] = exp2f(s[nt][3] - mBn);
            sumA += s[nt][0] + s[nt][1];
            sumB += s[nt][2] + s[nt][3];
        }
        sumA += __shfl_xor_sync(0xffffffffu, sumA, 1);
        sumA += __shfl_xor_sync(0xffffffffu, sumA, 2);
        sumB += __shfl_xor_sync(0xffffffffu, sumB, 1);
        sumB += __shfl_xor_sync(0xffffffffu, sumB, 2);

        lA = lA * fA + sumA;
        lB = lB * fB + sumB;
        mA = mAn; mB = mBn;
#pragma unroll
        for (int nt = 0; nt < 8; nt++) {
            o[nt][0] *= fA; o[nt][1] *= fA;
            o[nt][2] *= fB; o[nt][3] *= fB;
        }

        // ---- O += P @ V  (P from registers; V via ldmatrix.trans) ----
#pragma unroll
        for (int kc = 0; kc < 4; kc++) {
            uint32_t pa[4];
            pa[0] = packh2(s[2 * kc][0],     s[2 * kc][1]);
            pa[1] = packh2(s[2 * kc][2],     s[2 * kc][3]);
            pa[2] = packh2(s[2 * kc + 1][0], s[2 * kc + 1][1]);
            pa[3] = packh2(s[2 * kc + 1][2], s[2 * kc + 1][3]);
#pragma unroll
            for (int ntp = 0; ntp < 4; ntp++) {
                uint32_t b[4];
                ldm_x4_t(b, bV + voff + (uint32_t)(16 * kc * RW + ntp * 8) * 4);
                mma_f16(o[2 * ntp],     pa, b[0], b[1]);
                mma_f16(o[2 * ntp + 1], pa, b[2], b[3]);
            }
        }
    }

    // ---- epilogue: normalize, emit canonical fp16 words (proj-A input) ----
    float invA = 1.f / lA, invB = 1.f / lB;
    int rowA = q0 + warp * 16 + g;
#pragma unroll
    for (int nt = 0; nt < 8; nt++) {
        int hw = h * 32 + nt * 4 + tc;
        g_att[(size_t)rowA * KW + hw]       = packh2(o[nt][0] * invA, o[nt][1] * invA);
        g_att[(size_t)(rowA + 8) * KW + hw] = packh2(o[nt][2] * invB, o[nt][3] * invB);
    }
}

// ---------------------------------------------------------------------------
// Launch
// ---------------------------------------------------------------------------
extern "C" void kernel_launch(void* const* d_in, const int* in_sizes, int n_in,
                              void* d_out, int out_size)
{
    const float* x      = (const float*)d_in[0];
    const float* w_qkv  = (const float*)d_in[1];
    const float* w_proj = (const float*)d_in[2];
    float* out          = (float*)d_out;

    void *qkv_p, *att_p, *xw_p, *wqkvT_p, *wprojT_p;
    cudaGetSymbolAddress(&qkv_p,    g_qkv);
    cudaGetSymbolAddress(&att_p,    g_att);
    cudaGetSymbolAddress(&xw_p,     g_xw);
    cudaGetSymbolAddress(&wqkvT_p,  g_wqkvT);
    cudaGetSymbolAddress(&wprojT_p, g_wprojT);

    // 0) pre-process (canonical fp16)
    cvt_h<<<(TQ * KW / 4 + 255) / 256, 256>>>(x, (uint32_t*)xw_p, TQ * KW);
    wtrans_h<<<dim3(3 * DM / 32, DM / 32), dim3(32, 8)>>>(w_qkv, (uint32_t*)wqkvT_p,
                                                          DM, 3 * DM);
    wtrans_h<<<dim3(DM / 32, DM / 32), dim3(32, 8)>>>(w_proj, (uint32_t*)wprojT_p,
                                                      DM, DM);

    // 1) QKV projection (fp16 out; Q scaled by 0.125*log2e)
    gemm_h<1><<<dim3(3 * DM / 128, TQ / 128), 256>>>(
        (const uint32_t*)xw_p, (const uint32_t*)wqkvT_p, qkv_p, TQ, 3 * DM, KW);

    // 2) causal attention (64 q-rows/CTA, 4 warps)
    attn_fwd<<<dim3(TQ / 64, NH), 128>>>();

    // 3) output projection (fp32 out)
    gemm_h<0><<<dim3(DM / 128, TQ / 128), 256>>>(
        (const uint32_t*)att_p, (const uint32_t*)wprojT_p, out, TQ, DM, KW);
}

// round 11
// speedup vs baseline: 1.1509x; 1.0713x over previous
#include <cuda_runtime.h>
#include <cuda_fp16.h>
#include <cstdint>
#include <cmath>

#define TQ   4096
#define DM   1024
#define NH   16
#define DH   64
#define KW   (DM / 2)          // k-dim in fp16x2 words = 512

// Scratch (__device__ globals: allocation-free rule)
__device__ __half    g_qkv[(size_t)TQ * 3 * DM];     // [t][3c] fp16, Q pre-scaled (incl log2e)
__device__ uint32_t  g_att[(size_t)TQ * KW];         // attn out fp16 words (canonical)
__device__ uint32_t  g_xw[(size_t)TQ * KW];          // x fp16 words
__device__ uint32_t  g_wqkvT[(size_t)3 * DM * KW];   // w_qkv^T fp16 words [3DM][KW]
__device__ uint32_t  g_wprojT[(size_t)DM * KW];      // w_proj^T fp16 words [DM][KW]

// ---------------------------------------------------------------------------
// helpers
// ---------------------------------------------------------------------------
__device__ __forceinline__ uint32_t packh2(float a, float b) {
    __half2 h = __floats2half2_rn(a, b);
    return *reinterpret_cast<uint32_t*>(&h);
}

__device__ __forceinline__ void mma_f16(float* d, const uint32_t* a,
                                        uint32_t b0, uint32_t b1) {
    asm volatile(
        "mma.sync.aligned.m16n8k16.row.col.f32.f16.f16.f32 "
        "{%0,%1,%2,%3}, {%4,%5,%6,%7}, {%8,%9}, {%0,%1,%2,%3};\n"
        : "+f"(d[0]), "+f"(d[1]), "+f"(d[2]), "+f"(d[3])
        : "r"(a[0]), "r"(a[1]), "r"(a[2]), "r"(a[3]), "r"(b0), "r"(b1));
}

__device__ __forceinline__ void ldm_x4(uint32_t* r, uint32_t addr) {
    asm volatile("ldmatrix.sync.aligned.m8n8.x4.shared.b16 {%0,%1,%2,%3}, [%4];"
                 : "=r"(r[0]), "=r"(r[1]), "=r"(r[2]), "=r"(r[3]) : "r"(addr));
}
__device__ __forceinline__ void ldm_x4_t(uint32_t* r, uint32_t addr) {
    asm volatile("ldmatrix.sync.aligned.m8n8.x4.trans.shared.b16 {%0,%1,%2,%3}, [%4];"
                 : "=r"(r[0]), "=r"(r[1]), "=r"(r[2]), "=r"(r[3]) : "r"(addr));
}

__device__ __forceinline__ uint32_t s2u(const void* p) {
    uint32_t a;
    asm("{ .reg .u64 t; cvta.to.shared.u64 t, %1; cvt.u32.u64 %0, t; }"
        : "=r"(a) : "l"(p));
    return a;
}
__device__ __forceinline__ void cpa16(uint32_t dst, const void* src) {
    asm volatile("cp.async.cg.shared.global [%0], [%1], 16;\n" :: "r"(dst), "l"(src));
}
__device__ __forceinline__ void cpa_commit() {
    asm volatile("cp.async.commit_group;\n");
}
template <int N> __device__ __forceinline__ void cpa_wait() {
    asm volatile("cp.async.wait_group %0;\n" :: "n"(N));
}

// ---------------------------------------------------------------------------
// pre-processing (canonical layouts)
// ---------------------------------------------------------------------------
__global__ void cvt_h(const float* __restrict__ in, uint32_t* __restrict__ out,
                      int nwords)
{
    int i = blockIdx.x * blockDim.x + threadIdx.x;
    if (i * 4 >= nwords) return;
    const float4* p = (const float4*)(in + (size_t)i * 8);
    float4 v0 = p[0], v1 = p[1];
    uint4 w;
    w.x = packh2(v0.x, v0.y);
    w.y = packh2(v0.z, v0.w);
    w.z = packh2(v1.x, v1.y);
    w.w = packh2(v1.z, v1.w);
    *(uint4*)(out + (size_t)i * 4) = w;
}

// in [R][C] fp32 -> out [C][R/2 words] fp16x2 (canonical).
__global__ void wtrans_h(const float* __restrict__ in, uint32_t* __restrict__ out,
                         int R, int C)
{
    __shared__ float t[32][33];
    int c0 = blockIdx.x * 32, r0 = blockIdx.y * 32;
    int tx = threadIdx.x, ty = threadIdx.y;
#pragma unroll
    for (int i = 0; i < 4; i++)
        t[ty + 8 * i][tx] = in[(size_t)(r0 + ty + 8 * i) * C + c0 + tx];
    __syncthreads();
    int Rw = R / 2;
#pragma unroll
    for (int i = 0; i < 2; i++) {
        int wp = ty + 8 * i;
        out[(size_t)(c0 + tx) * Rw + r0 / 2 + wp] =
            packh2(t[2 * wp][tx], t[2 * wp + 1][tx]);
    }
}

// ---------------------------------------------------------------------------
// fp16 GEMM, ldmatrix + XOR-swizzled smem, 3-stage single-sync pipeline.
// C[M,N] = A[M,K] @ B[N,K]^T. BM=128, BN=128, stage = 32 words (K=64),
// 256 thr (4 warps M x 2 warps N, warp tile 32x64).
// smem word addr for (row r, 16B-chunk ch): r*32 + ((ch ^ (r&7)) << 2).
// MODE 1 (qkv): fp16 word output; Q cols (<DM) scaled by 0.125*log2e.
// ---------------------------------------------------------------------------
#define GOPER  (128 * 32)            // words per operand per stage
#define GSTAGE (2 * GOPER)           // words per stage (A then B)
#define QSCALE (0.125f * 1.4426950408889634f)

template <int MODE>
__global__ __launch_bounds__(256, 2)
void gemm_h(const uint32_t* __restrict__ A, const uint32_t* __restrict__ B,
            void* __restrict__ Cv, int M, int N, int Kw)
{
    __shared__ __align__(16) uint32_t sm[3 * GSTAGE];   // 96 KB
    const uint32_t s0 = s2u(sm);

    const int tid  = threadIdx.x;
    const int lane = tid & 31;
    const int warp = tid >> 5;
    const int wm   = warp & 3;
    const int wn   = warp >> 2;
    const int bx   = blockIdx.x;
    const int by   = blockIdx.y;
    const int g    = lane >> 2;
    const int tc   = lane & 3;

    const uint32_t* Ab = A + (size_t)(by * 128) * Kw;
    const uint32_t* Bb = B + (size_t)(bx * 128) * Kw;

    float acc[2][8][4];
#pragma unroll
    for (int mt = 0; mt < 2; mt++)
#pragma unroll
        for (int nt = 0; nt < 8; nt++)
#pragma unroll
            for (int j = 0; j < 4; j++) acc[mt][nt][j] = 0.f;

    auto load_stage = [&](int s, int buf) {
        uint32_t dA = s0 + (uint32_t)(buf * GSTAGE) * 4;
        uint32_t dB = dA + (uint32_t)GOPER * 4;
#pragma unroll
        for (int j = 0; j < 4; j++) {
            int idx = tid + j * 256;
            int r = idx >> 3, ch = idx & 7;
            uint32_t sw = ((uint32_t)(r * 32) + ((ch ^ (r & 7)) << 2)) * 4;  // bytes
            cpa16(dA + sw, Ab + (size_t)r * Kw + s * 32 + ch * 4);
            cpa16(dB + sw, Bb + (size_t)r * Kw + s * 32 + ch * 4);
        }
        cpa_commit();
    };

    load_stage(0, 0);
    load_stage(1, 1);

    // per-thread ldmatrix components (loop-invariant)
    const int arow  = wm * 32 + (lane & 15);
    const int ahi   = lane >> 4;
    const int brow  = wn * 64 + (lane & 7) + ((lane >> 4) << 3);
    const int bhi   = (lane >> 3) & 1;
    uint32_t abase  = (uint32_t)(arow * 32) * 4;         // bytes
    uint32_t bbase  = (uint32_t)(brow * 32) * 4;
    uint32_t aswz[4], bswz[4];
#pragma unroll
    for (int ks = 0; ks < 4; ks++) {
        aswz[ks] = (uint32_t)(((2 * ks + ahi) ^ (arow & 7)) << 4);  // bytes
        bswz[ks] = (uint32_t)(((2 * ks + bhi) ^ (brow & 7)) << 4);
    }

    const int S = Kw / 32;
    int buf = 0;
    for (int s = 0; s < S; s++) {
        if (s + 1 < S) cpa_wait<1>(); else cpa_wait<0>();
        __syncthreads();
        if (s + 2 < S) {
            int nb = buf + 2;
            if (nb >= 3) nb -= 3;           // correct ring advance
            load_stage(s + 2, nb);
        }

        const uint32_t bA = s0 + (uint32_t)(buf * GSTAGE) * 4;
        const uint32_t bB = bA + (uint32_t)GOPER * 4;

#pragma unroll
        for (int ks = 0; ks < 4; ks++) {
            uint32_t a[2][4];
            ldm_x4(a[0], bA + abase + aswz[ks]);
            ldm_x4(a[1], bA + abase + (uint32_t)(16 * 32 * 4) + aswz[ks]);
#pragma unroll
            for (int nt2 = 0; nt2 < 4; nt2++) {
                uint32_t b[4];
                ldm_x4(b, bB + bbase + (uint32_t)(nt2 * 16 * 32 * 4) + bswz[ks]);
                mma_f16(acc[0][2 * nt2],     a[0], b[0], b[1]);
                mma_f16(acc[1][2 * nt2],     a[1], b[0], b[1]);
                mma_f16(acc[0][2 * nt2 + 1], a[0], b[2], b[3]);
                mma_f16(acc[1][2 * nt2 + 1], a[1], b[2], b[3]);
            }
        }
        buf = (buf + 1 == 3) ? 0 : buf + 1;
    }

    // epilogue
#pragma unroll
    for (int mt = 0; mt < 2; mt++)
#pragma unroll
        for (int nt = 0; nt < 8; nt++) {
            int r0 = by * 128 + wm * 32 + mt * 16 + g;
            int c0 = bx * 128 + wn * 64 + nt * 8 + 2 * tc;
            float v0 = acc[mt][nt][0], v1 = acc[mt][nt][1];
            float v2 = acc[mt][nt][2], v3 = acc[mt][nt][3];
            if (MODE == 1) {
                float sc = (c0 < DM) ? QSCALE : 1.0f;   // Q: fold 1/8 and log2e
                uint32_t* C = (uint32_t*)Cv;
                int cw = c0 >> 1;
                C[(size_t)r0 * (N / 2) + cw]       = packh2(v0 * sc, v1 * sc);
                C[(size_t)(r0 + 8) * (N / 2) + cw] = packh2(v2 * sc, v3 * sc);
            } else {
                float* C = (float*)Cv;
                *(float2*)(C + (size_t)r0 * N + c0)       = make_float2(v0, v1);
                *(float2*)(C + (size_t)(r0 + 8) * N + c0) = make_float2(v2, v3);
            }
        }
}

// ---------------------------------------------------------------------------
// Causal flash attention, fp16 mma m16n8k16. 64 q-rows, 4 warps (proven
// best shape). Scores in log2 units -> exp2f softmax. P passes S->PV in
// registers; V via ldmatrix.trans. smem 27.6 KB. (unchanged from round 9)
// ---------------------------------------------------------------------------
#define RW 36
__global__ __launch_bounds__(128) void attn_fwd()
{
    __shared__ __align__(16) uint32_t smQ[64 * RW];
    __shared__ __align__(16) uint32_t smK[64 * RW];
    __shared__ __align__(16) uint32_t smV[64 * RW];
    const uint32_t bQ = s2u(smQ), bK = s2u(smK), bV = s2u(smV);

    const int tid  = threadIdx.x;
    const int lane = tid & 31;
    const int warp = tid >> 5;
    const int h    = blockIdx.y;
    const int qt   = (int)gridDim.x - 1 - (int)blockIdx.x;  // heavy tiles first
    const int q0   = qt * 64;
    const int g    = lane >> 2;
    const int tc   = lane & 3;

    // ---- prologue: Q tile ----
#pragma unroll
    for (int i = 0; i < 4; i++) {
        int idx = tid + i * 128;
        int r = idx >> 3, ch = idx & 7;
        cpa16(bQ + (uint32_t)(r * RW + ch * 4) * 4,
              g_qkv + (size_t)(q0 + r) * (3 * DM) + h * DH + ch * 8);
    }
    cpa_commit();

    const uint32_t qoff = (uint32_t)((warp * 16 + (lane & 15)) * RW +
                                     ((lane >> 4) << 2)) * 4;
    const uint32_t koff = (uint32_t)(((lane & 7) + ((lane >> 4) << 3)) * RW +
                                     (((lane >> 3) & 1) << 2)) * 4;
    const uint32_t voff = (uint32_t)((lane & 15) * RW + ((lane >> 4) << 2)) * 4;

    float o[8][4];
#pragma unroll
    for (int nt = 0; nt < 8; nt++)
#pragma unroll
        for (int j = 0; j < 4; j++) o[nt][j] = 0.f;
    float mA = -INFINITY, mB = -INFINITY, lA = 0.f, lB = 0.f;

    for (int t = 0; t <= qt; t++) {
        __syncthreads();
#pragma unroll
        for (int i = 0; i < 4; i++) {
            int idx = tid + i * 128;
            int r = idx >> 3, ch = idx & 7;
            const __half* base = g_qkv + (size_t)(t * 64 + r) * (3 * DM) + h * DH + ch * 8;
            cpa16(bK + (uint32_t)(r * RW + ch * 4) * 4, base + DM);
            cpa16(bV + (uint32_t)(r * RW + ch * 4) * 4, base + 2 * DM);
        }
        cpa_commit();
        cpa_wait<0>();
        __syncthreads();

        // ---- S = Q @ K^T ----
        float s[8][4];
#pragma unroll
        for (int nt = 0; nt < 8; nt++)
#pragma unroll
            for (int j = 0; j < 4; j++) s[nt][j] = 0.f;

#pragma unroll
        for (int kc = 0; kc < 4; kc++) {
            uint32_t a[4];
            ldm_x4(a, bQ + qoff + (uint32_t)(8 * kc) * 4);
#pragma unroll
            for (int ntp = 0; ntp < 4; ntp++) {
                uint32_t b[4];
                ldm_x4(b, bK + koff + (uint32_t)(ntp * 16 * RW + 8 * kc) * 4);
                mma_f16(s[2 * ntp],     a, b[0], b[1]);
                mma_f16(s[2 * ntp + 1], a, b[2], b[3]);
            }
        }

        // ---- causal mask on diagonal tile ----
        if (t == qt) {
            int qlA = warp * 16 + g;
            int qlB = qlA + 8;
#pragma unroll
            for (int nt = 0; nt < 8; nt++) {
                int k0 = nt * 8 + 2 * tc;
                if (k0     > qlA) s[nt][0] = -INFINITY;
                if (k0 + 1 > qlA) s[nt][1] = -INFINITY;
                if (k0     > qlB) s[nt][2] = -INFINITY;
                if (k0 + 1 > qlB) s[nt][3] = -INFINITY;
            }
        }

        // ---- online softmax (base-2) ----
        float rA = -INFINITY, rB = -INFINITY;
#pragma unroll
        for (int nt = 0; nt < 8; nt++) {
            rA = fmaxf(rA, fmaxf(s[nt][0], s[nt][1]));
            rB = fmaxf(rB, fmaxf(s[nt][2], s[nt][3]));
        }
        rA = fmaxf(rA, __shfl_xor_sync(0xffffffffu, rA, 1));
        rA = fmaxf(rA, __shfl_xor_sync(0xffffffffu, rA, 2));
        rB = fmaxf(rB, __shfl_xor_sync(0xffffffffu, rB, 1));
        rB = fmaxf(rB, __shfl_xor_sync(0xffffffffu, rB, 2));

        float mAn = fmaxf(mA, rA), mBn = fmaxf(mB, rB);
        float fA = exp2f(mA - mAn), fB = exp2f(mB - mBn);

        float sumA = 0.f, sumB = 0.f;
#pragma unroll
        for (int nt = 0; nt < 8; nt++) {
            s[nt][0] = exp2f(s[nt][0] - mAn);
            s[nt][1] = exp2f(s[nt][1] - mAn);
            s[nt][2] = exp2f(s[nt][2] - mBn);
            s[nt][3] = exp2f(s[nt][3] - mBn);
            sumA += s[nt][0] + s[nt][1];
            sumB += s[nt][2] + s[nt][3];
        }
        sumA += __shfl_xor_sync(0xffffffffu, sumA, 1);
        sumA += __shfl_xor_sync(0xffffffffu, sumA, 2);
        sumB += __shfl_xor_sync(0xffffffffu, sumB, 1);
        sumB += __shfl_xor_sync(0xffffffffu, sumB, 2);

        lA = lA * fA + sumA;
        lB = lB * fB + sumB;
        mA = mAn; mB = mBn;
#pragma unroll
        for (int nt = 0; nt < 8; nt++) {
            o[nt][0] *= fA; o[nt][1] *= fA;
            o[nt][2] *= fB; o[nt][3] *= fB;
        }

        // ---- O += P @ V ----
#pragma unroll
        for (int kc = 0; kc < 4; kc++) {
            uint32_t pa[4];
            pa[0] = packh2(s[2 * kc][0],     s[2 * kc][1]);
            pa[1] = packh2(s[2 * kc][2],     s[2 * kc][3]);
            pa[2] = packh2(s[2 * kc + 1][0], s[2 * kc + 1][1]);
            pa[3] = packh2(s[2 * kc + 1][2], s[2 * kc + 1][3]);
#pragma unroll
            for (int ntp = 0; ntp < 4; ntp++) {
                uint32_t b[4];
                ldm_x4_t(b, bV + voff + (uint32_t)(16 * kc * RW + ntp * 8) * 4);
                mma_f16(o[2 * ntp],     pa, b[0], b[1]);
                mma_f16(o[2 * ntp + 1], pa, b[2], b[3]);
            }
        }
    }

    // ---- epilogue: normalize, emit canonical fp16 words (proj-A input) ----
    float invA = 1.f / lA, invB = 1.f / lB;
    int rowA = q0 + warp * 16 + g;
#pragma unroll
    for (int nt = 0; nt < 8; nt++) {
        int hw = h * 32 + nt * 4 + tc;
        g_att[(size_t)rowA * KW + hw]       = packh2(o[nt][0] * invA, o[nt][1] * invA);
        g_att[(size_t)(rowA + 8) * KW + hw] = packh2(o[nt][2] * invB, o[nt][3] * invB);
    }
}

// ---------------------------------------------------------------------------
// Launch
// ---------------------------------------------------------------------------
extern "C" void kernel_launch(void* const* d_in, const int* in_sizes, int n_in,
                              void* d_out, int out_size)
{
    const float* x      = (const float*)d_in[0];
    const float* w_qkv  = (const float*)d_in[1];
    const float* w_proj = (const float*)d_in[2];
    float* out          = (float*)d_out;

    void *qkv_p, *att_p, *xw_p, *wqkvT_p, *wprojT_p;
    cudaGetSymbolAddress(&qkv_p,    g_qkv);
    cudaGetSymbolAddress(&att_p,    g_att);
    cudaGetSymbolAddress(&xw_p,     g_xw);
    cudaGetSymbolAddress(&wqkvT_p,  g_wqkvT);
    cudaGetSymbolAddress(&wprojT_p, g_wprojT);

    // 0) pre-process (canonical fp16)
    cvt_h<<<(TQ * KW / 4 + 255) / 256, 256>>>(x, (uint32_t*)xw_p, TQ * KW);
    wtrans_h<<<dim3(3 * DM / 32, DM / 32), dim3(32, 8)>>>(w_qkv, (uint32_t*)wqkvT_p,
                                                          DM, 3 * DM);
    wtrans_h<<<dim3(DM / 32, DM / 32), dim3(32, 8)>>>(w_proj, (uint32_t*)wprojT_p,
                                                      DM, DM);

    // 1) QKV projection (fp16 out; Q scaled by 0.125*log2e)
    gemm_h<1><<<dim3(3 * DM / 128, TQ / 128), 256>>>(
        (const uint32_t*)xw_p, (const uint32_t*)wqkvT_p, qkv_p, TQ, 3 * DM, KW);

    // 2) causal attention (64 q-rows/CTA, 4 warps)
    attn_fwd<<<dim3(TQ / 64, NH), 128>>>();

    // 3) output projection (fp32 out)
    gemm_h<0><<<dim3(DM / 128, TQ / 128), 256>>>(
        (const uint32_t*)att_p, (const uint32_t*)wprojT_p, out, TQ, DM, KW);
}

// round 12
// speedup vs baseline: 1.1809x; 1.0260x over previous
#include <cuda_runtime.h>
#include <cuda_fp16.h>
#include <cstdint>
#include <cmath>

#define TQ   4096
#define DM   1024
#define NH   16
#define DH   64
#define KW   (DM / 2)          // k-dim in fp16x2 words = 512

// Scratch (__device__ globals: allocation-free rule)
__device__ __half    g_qkv[(size_t)TQ * 3 * DM];     // [t][3c] fp16, Q pre-scaled (incl log2e)
__device__ uint32_t  g_att[(size_t)TQ * KW];         // attn out fp16 words (canonical)
__device__ uint32_t  g_xw[(size_t)TQ * KW];          // x fp16 words
__device__ uint32_t  g_wqkvT[(size_t)3 * DM * KW];   // w_qkv^T fp16 words [3DM][KW]
__device__ uint32_t  g_wprojT[(size_t)DM * KW];      // w_proj^T fp16 words [DM][KW]

// ---------------------------------------------------------------------------
// helpers
// ---------------------------------------------------------------------------
__device__ __forceinline__ uint32_t packh2(float a, float b) {
    __half2 h = __floats2half2_rn(a, b);
    return *reinterpret_cast<uint32_t*>(&h);
}
__device__ __forceinline__ uint32_t h2exp2u(uint32_t x) {   // 2^x on both halves
    uint32_t r;
    asm("ex2.approx.f16x2 %0, %1;" : "=r"(r) : "r"(x));
    return r;
}

__device__ __forceinline__ void mma_f16(float* d, const uint32_t* a,
                                        uint32_t b0, uint32_t b1) {
    asm volatile(
        "mma.sync.aligned.m16n8k16.row.col.f32.f16.f16.f32 "
        "{%0,%1,%2,%3}, {%4,%5,%6,%7}, {%8,%9}, {%0,%1,%2,%3};\n"
        : "+f"(d[0]), "+f"(d[1]), "+f"(d[2]), "+f"(d[3])
        : "r"(a[0]), "r"(a[1]), "r"(a[2]), "r"(a[3]), "r"(b0), "r"(b1));
}

__device__ __forceinline__ void ldm_x4(uint32_t* r, uint32_t addr) {
    asm volatile("ldmatrix.sync.aligned.m8n8.x4.shared.b16 {%0,%1,%2,%3}, [%4];"
                 : "=r"(r[0]), "=r"(r[1]), "=r"(r[2]), "=r"(r[3]) : "r"(addr));
}
__device__ __forceinline__ void ldm_x4_t(uint32_t* r, uint32_t addr) {
    asm volatile("ldmatrix.sync.aligned.m8n8.x4.trans.shared.b16 {%0,%1,%2,%3}, [%4];"
                 : "=r"(r[0]), "=r"(r[1]), "=r"(r[2]), "=r"(r[3]) : "r"(addr));
}

__device__ __forceinline__ uint32_t s2u(const void* p) {
    uint32_t a;
    asm("{ .reg .u64 t; cvta.to.shared.u64 t, %1; cvt.u32.u64 %0, t; }"
        : "=r"(a) : "l"(p));
    return a;
}
__device__ __forceinline__ void cpa16(uint32_t dst, const void* src) {
    asm volatile("cp.async.cg.shared.global [%0], [%1], 16;\n" :: "r"(dst), "l"(src));
}
__device__ __forceinline__ void cpa_commit() {
    asm volatile("cp.async.commit_group;\n");
}
template <int N> __device__ __forceinline__ void cpa_wait() {
    asm volatile("cp.async.wait_group %0;\n" :: "n"(N));
}

// ---------------------------------------------------------------------------
// pre-processing (canonical layouts)
// ---------------------------------------------------------------------------
__global__ void cvt_h(const float* __restrict__ in, uint32_t* __restrict__ out,
                      int nwords)
{
    int i = blockIdx.x * blockDim.x + threadIdx.x;
    if (i * 4 >= nwords) return;
    const float4* p = (const float4*)(in + (size_t)i * 8);
    float4 v0 = p[0], v1 = p[1];
    uint4 w;
    w.x = packh2(v0.x, v0.y);
    w.y = packh2(v0.z, v0.w);
    w.z = packh2(v1.x, v1.y);
    w.w = packh2(v1.z, v1.w);
    *(uint4*)(out + (size_t)i * 4) = w;
}

// in [R][C] fp32 -> out [C][R/2 words] fp16x2 (canonical).
__global__ void wtrans_h(const float* __restrict__ in, uint32_t* __restrict__ out,
                         int R, int C)
{
    __shared__ float t[32][33];
    int c0 = blockIdx.x * 32, r0 = blockIdx.y * 32;
    int tx = threadIdx.x, ty = threadIdx.y;
#pragma unroll
    for (int i = 0; i < 4; i++)
        t[ty + 8 * i][tx] = in[(size_t)(r0 + ty + 8 * i) * C + c0 + tx];
    __syncthreads();
    int Rw = R / 2;
#pragma unroll
    for (int i = 0; i < 2; i++) {
        int wp = ty + 8 * i;
        out[(size_t)(c0 + tx) * Rw + r0 / 2 + wp] =
            packh2(t[2 * wp][tx], t[2 * wp + 1][tx]);
    }
}

// ---------------------------------------------------------------------------
// fp16 GEMM, ldmatrix + XOR-swizzled smem, 3-stage single-sync pipeline.
// (unchanged from round 11)
// ---------------------------------------------------------------------------
#define GOPER  (128 * 32)            // words per operand per stage
#define GSTAGE (2 * GOPER)           // words per stage (A then B)
#define QSCALE (0.125f * 1.4426950408889634f)

template <int MODE>
__global__ __launch_bounds__(256, 2)
void gemm_h(const uint32_t* __restrict__ A, const uint32_t* __restrict__ B,
            void* __restrict__ Cv, int M, int N, int Kw)
{
    __shared__ __align__(16) uint32_t sm[3 * GSTAGE];   // 96 KB
    const uint32_t s0 = s2u(sm);

    const int tid  = threadIdx.x;
    const int lane = tid & 31;
    const int warp = tid >> 5;
    const int wm   = warp & 3;
    const int wn   = warp >> 2;
    const int bx   = blockIdx.x;
    const int by   = blockIdx.y;
    const int g    = lane >> 2;
    const int tc   = lane & 3;

    const uint32_t* Ab = A + (size_t)(by * 128) * Kw;
    const uint32_t* Bb = B + (size_t)(bx * 128) * Kw;

    float acc[2][8][4];
#pragma unroll
    for (int mt = 0; mt < 2; mt++)
#pragma unroll
        for (int nt = 0; nt < 8; nt++)
#pragma unroll
            for (int j = 0; j < 4; j++) acc[mt][nt][j] = 0.f;

    auto load_stage = [&](int s, int buf) {
        uint32_t dA = s0 + (uint32_t)(buf * GSTAGE) * 4;
        uint32_t dB = dA + (uint32_t)GOPER * 4;
#pragma unroll
        for (int j = 0; j < 4; j++) {
            int idx = tid + j * 256;
            int r = idx >> 3, ch = idx & 7;
            uint32_t sw = ((uint32_t)(r * 32) + ((ch ^ (r & 7)) << 2)) * 4;  // bytes
            cpa16(dA + sw, Ab + (size_t)r * Kw + s * 32 + ch * 4);
            cpa16(dB + sw, Bb + (size_t)r * Kw + s * 32 + ch * 4);
        }
        cpa_commit();
    };

    load_stage(0, 0);
    load_stage(1, 1);

    const int arow  = wm * 32 + (lane & 15);
    const int ahi   = lane >> 4;
    const int brow  = wn * 64 + (lane & 7) + ((lane >> 4) << 3);
    const int bhi   = (lane >> 3) & 1;
    uint32_t abase  = (uint32_t)(arow * 32) * 4;
    uint32_t bbase  = (uint32_t)(brow * 32) * 4;
    uint32_t aswz[4], bswz[4];
#pragma unroll
    for (int ks = 0; ks < 4; ks++) {
        aswz[ks] = (uint32_t)(((2 * ks + ahi) ^ (arow & 7)) << 4);
        bswz[ks] = (uint32_t)(((2 * ks + bhi) ^ (brow & 7)) << 4);
    }

    const int S = Kw / 32;
    int buf = 0;
    for (int s = 0; s < S; s++) {
        if (s + 1 < S) cpa_wait<1>(); else cpa_wait<0>();
        __syncthreads();
        if (s + 2 < S) {
            int nb = buf + 2;
            if (nb >= 3) nb -= 3;
            load_stage(s + 2, nb);
        }

        const uint32_t bA = s0 + (uint32_t)(buf * GSTAGE) * 4;
        const uint32_t bB = bA + (uint32_t)GOPER * 4;

#pragma unroll
        for (int ks = 0; ks < 4; ks++) {
            uint32_t a[2][4];
            ldm_x4(a[0], bA + abase + aswz[ks]);
            ldm_x4(a[1], bA + abase + (uint32_t)(16 * 32 * 4) + aswz[ks]);
#pragma unroll
            for (int nt2 = 0; nt2 < 4; nt2++) {
                uint32_t b[4];
                ldm_x4(b, bB + bbase + (uint32_t)(nt2 * 16 * 32 * 4) + bswz[ks]);
                mma_f16(acc[0][2 * nt2],     a[0], b[0], b[1]);
                mma_f16(acc[1][2 * nt2],     a[1], b[0], b[1]);
                mma_f16(acc[0][2 * nt2 + 1], a[0], b[2], b[3]);
                mma_f16(acc[1][2 * nt2 + 1], a[1], b[2], b[3]);
            }
        }
        buf = (buf + 1 == 3) ? 0 : buf + 1;
    }

    // epilogue
#pragma unroll
    for (int mt = 0; mt < 2; mt++)
#pragma unroll
        for (int nt = 0; nt < 8; nt++) {
            int r0 = by * 128 + wm * 32 + mt * 16 + g;
            int c0 = bx * 128 + wn * 64 + nt * 8 + 2 * tc;
            float v0 = acc[mt][nt][0], v1 = acc[mt][nt][1];
            float v2 = acc[mt][nt][2], v3 = acc[mt][nt][3];
            if (MODE == 1) {
                float sc = (c0 < DM) ? QSCALE : 1.0f;   // Q: fold 1/8 and log2e
                uint32_t* C = (uint32_t*)Cv;
                int cw = c0 >> 1;
                C[(size_t)r0 * (N / 2) + cw]       = packh2(v0 * sc, v1 * sc);
                C[(size_t)(r0 + 8) * (N / 2) + cw] = packh2(v2 * sc, v3 * sc);
            } else {
                float* C = (float*)Cv;
                *(float2*)(C + (size_t)r0 * N + c0)       = make_float2(v0, v1);
                *(float2*)(C + (size_t)(r0 + 8) * N + c0) = make_float2(v2, v3);
            }
        }
}

// ---------------------------------------------------------------------------
// Causal flash attention, fp16 mma m16n8k16. 64 q-rows, 4 warps.
// Scores in log2 units. Softmax: fp16x2 ex2.approx (exp output IS the PV
// A-fragment) + row sums via ones-MMA (no shuffles). smem 27.6 KB.
// ---------------------------------------------------------------------------
#define RW 36
#define ONE2 0x3C003C00u            // (1.0h, 1.0h)
__global__ __launch_bounds__(128) void attn_fwd()
{
    __shared__ __align__(16) uint32_t smQ[64 * RW];
    __shared__ __align__(16) uint32_t smK[64 * RW];
    __shared__ __align__(16) uint32_t smV[64 * RW];
    const uint32_t bQ = s2u(smQ), bK = s2u(smK), bV = s2u(smV);

    const int tid  = threadIdx.x;
    const int lane = tid & 31;
    const int warp = tid >> 5;
    const int h    = blockIdx.y;
    const int qt   = (int)gridDim.x - 1 - (int)blockIdx.x;  // heavy tiles first
    const int q0   = qt * 64;
    const int g    = lane >> 2;
    const int tc   = lane & 3;

    // ---- prologue: Q tile ----
#pragma unroll
    for (int i = 0; i < 4; i++) {
        int idx = tid + i * 128;
        int r = idx >> 3, ch = idx & 7;
        cpa16(bQ + (uint32_t)(r * RW + ch * 4) * 4,
              g_qkv + (size_t)(q0 + r) * (3 * DM) + h * DH + ch * 8);
    }
    cpa_commit();

    const uint32_t qoff = (uint32_t)((warp * 16 + (lane & 15)) * RW +
                                     ((lane >> 4) << 2)) * 4;
    const uint32_t koff = (uint32_t)(((lane & 7) + ((lane >> 4) << 3)) * RW +
                                     (((lane >> 3) & 1) << 2)) * 4;
    const uint32_t voff = (uint32_t)((lane & 15) * RW + ((lane >> 4) << 2)) * 4;

    float o[8][4];
#pragma unroll
    for (int nt = 0; nt < 8; nt++)
#pragma unroll
        for (int j = 0; j < 4; j++) o[nt][j] = 0.f;
    float mA = -INFINITY, mB = -INFINITY, lA = 0.f, lB = 0.f;

    for (int t = 0; t <= qt; t++) {
        __syncthreads();
#pragma unroll
        for (int i = 0; i < 4; i++) {
            int idx = tid + i * 128;
            int r = idx >> 3, ch = idx & 7;
            const __half* base = g_qkv + (size_t)(t * 64 + r) * (3 * DM) + h * DH + ch * 8;
            cpa16(bK + (uint32_t)(r * RW + ch * 4) * 4, base + DM);
            cpa16(bV + (uint32_t)(r * RW + ch * 4) * 4, base + 2 * DM);
        }
        cpa_commit();
        cpa_wait<0>();
        __syncthreads();

        // ---- S = Q @ K^T (log2-unit scores) ----
        float s[8][4];
#pragma unroll
        for (int nt = 0; nt < 8; nt++)
#pragma unroll
            for (int j = 0; j < 4; j++) s[nt][j] = 0.f;

#pragma unroll
        for (int kc = 0; kc < 4; kc++) {
            uint32_t a[4];
            ldm_x4(a, bQ + qoff + (uint32_t)(8 * kc) * 4);
#pragma unroll
            for (int ntp = 0; ntp < 4; ntp++) {
                uint32_t b[4];
                ldm_x4(b, bK + koff + (uint32_t)(ntp * 16 * RW + 8 * kc) * 4);
                mma_f16(s[2 * ntp],     a, b[0], b[1]);
                mma_f16(s[2 * ntp + 1], a, b[2], b[3]);
            }
        }

        // ---- causal mask on diagonal tile ----
        if (t == qt) {
            int qlA = warp * 16 + g;
            int qlB = qlA + 8;
#pragma unroll
            for (int nt = 0; nt < 8; nt++) {
                int k0 = nt * 8 + 2 * tc;
                if (k0     > qlA) s[nt][0] = -INFINITY;
                if (k0 + 1 > qlA) s[nt][1] = -INFINITY;
                if (k0     > qlB) s[nt][2] = -INFINITY;
                if (k0 + 1 > qlB) s[nt][3] = -INFINITY;
            }
        }

        // ---- row max (fp32, shuffles) ----
        float rA = -INFINITY, rB = -INFINITY;
#pragma unroll
        for (int nt = 0; nt < 8; nt++) {
            rA = fmaxf(rA, fmaxf(s[nt][0], s[nt][1]));
            rB = fmaxf(rB, fmaxf(s[nt][2], s[nt][3]));
        }
        rA = fmaxf(rA, __shfl_xor_sync(0xffffffffu, rA, 1));
        rA = fmaxf(rA, __shfl_xor_sync(0xffffffffu, rA, 2));
        rB = fmaxf(rB, __shfl_xor_sync(0xffffffffu, rB, 1));
        rB = fmaxf(rB, __shfl_xor_sync(0xffffffffu, rB, 2));

        float mAn = fmaxf(mA, rA), mBn = fmaxf(mB, rB);
        float fA = exp2f(mA - mAn), fB = exp2f(mB - mBn);

        // ---- exp in fp16x2; row sums via ones-MMA (exact fp32 accumulate) ----
        uint32_t pw[4][4];
        float dl[4] = {0.f, 0.f, 0.f, 0.f};
#pragma unroll
        for (int kc = 0; kc < 4; kc++) {
            pw[kc][0] = h2exp2u(packh2(s[2 * kc][0] - mAn,     s[2 * kc][1] - mAn));
            pw[kc][1] = h2exp2u(packh2(s[2 * kc][2] - mBn,     s[2 * kc][3] - mBn));
            pw[kc][2] = h2exp2u(packh2(s[2 * kc + 1][0] - mAn, s[2 * kc + 1][1] - mAn));
            pw[kc][3] = h2exp2u(packh2(s[2 * kc + 1][2] - mBn, s[2 * kc + 1][3] - mBn));
            mma_f16(dl, pw[kc], ONE2, ONE2);
        }

        lA = lA * fA + dl[0];
        lB = lB * fB + dl[2];
        mA = mAn; mB = mBn;
#pragma unroll
        for (int nt = 0; nt < 8; nt++) {
            o[nt][0] *= fA; o[nt][1] *= fA;
            o[nt][2] *= fB; o[nt][3] *= fB;
        }

        // ---- O += P @ V  (P = pw, already fp16; V via ldmatrix.trans) ----
#pragma unroll
        for (int kc = 0; kc < 4; kc++) {
#pragma unroll
            for (int ntp = 0; ntp < 4; ntp++) {
                uint32_t b[4];
                ldm_x4_t(b, bV + voff + (uint32_t)(16 * kc * RW + ntp * 8) * 4);
                mma_f16(o[2 * ntp],     pw[kc], b[0], b[1]);
                mma_f16(o[2 * ntp + 1], pw[kc], b[2], b[3]);
            }
        }
    }

    // ---- epilogue: normalize, emit canonical fp16 words (proj-A input) ----
    float invA = 1.f / lA, invB = 1.f / lB;
    int rowA = q0 + warp * 16 + g;
#pragma unroll
    for (int nt = 0; nt < 8; nt++) {
        int hw = h * 32 + nt * 4 + tc;
        g_att[(size_t)rowA * KW + hw]       = packh2(o[nt][0] * invA, o[nt][1] * invA);
        g_att[(size_t)(rowA + 8) * KW + hw] = packh2(o[nt][2] * invB, o[nt][3] * invB);
    }
}

// ---------------------------------------------------------------------------
// Launch
// ---------------------------------------------------------------------------
extern "C" void kernel_launch(void* const* d_in, const int* in_sizes, int n_in,
                              void* d_out, int out_size)
{
    const float* x      = (const float*)d_in[0];
    const float* w_qkv  = (const float*)d_in[1];
    const float* w_proj = (const float*)d_in[2];
    float* out          = (float*)d_out;

    void *qkv_p, *att_p, *xw_p, *wqkvT_p, *wprojT_p;
    cudaGetSymbolAddress(&qkv_p,    g_qkv);
    cudaGetSymbolAddress(&att_p,    g_att);
    cudaGetSymbolAddress(&xw_p,     g_xw);
    cudaGetSymbolAddress(&wqkvT_p,  g_wqkvT);
    cudaGetSymbolAddress(&wprojT_p, g_wprojT);

    // 0) pre-process (canonical fp16)
    cvt_h<<<(TQ * KW / 4 + 255) / 256, 256>>>(x, (uint32_t*)xw_p, TQ * KW);
    wtrans_h<<<dim3(3 * DM / 32, DM / 32), dim3(32, 8)>>>(w_qkv, (uint32_t*)wqkvT_p,
                                                          DM, 3 * DM);
    wtrans_h<<<dim3(DM / 32, DM / 32), dim3(32, 8)>>>(w_proj, (uint32_t*)wprojT_p,
                                                      DM, DM);

    // 1) QKV projection (fp16 out; Q scaled by 0.125*log2e)
    gemm_h<1><<<dim3(3 * DM / 128, TQ / 128), 256>>>(
        (const uint32_t*)xw_p, (const uint32_t*)wqkvT_p, qkv_p, TQ, 3 * DM, KW);

    // 2) causal attention (64 q-rows/CTA, 4 warps)
    attn_fwd<<<dim3(TQ / 64, NH), 128>>>();

    // 3) output projection (fp32 out)
    gemm_h<0><<<dim3(DM / 128, TQ / 128), 256>>>(
        (const uint32_t*)att_p, (const uint32_t*)wprojT_p, out, TQ, DM, KW);
}

// round 13
// speedup vs baseline: 1.2211x; 1.0341x over previous
#include <cuda_runtime.h>
#include <cuda_fp16.h>
#include <cstdint>
#include <cmath>

#define TQ   4096
#define DM   1024
#define NH   16
#define DH   64
#define KW   (DM / 2)          // k-dim in fp16x2 words = 512

// Scratch (__device__ globals: allocation-free rule)
__device__ __half    g_qkv[(size_t)TQ * 3 * DM];     // [t][3c] fp16, Q pre-scaled (incl log2e)
__device__ uint32_t  g_att[(size_t)TQ * KW];         // attn out fp16 words (canonical)
__device__ uint32_t  g_xw[(size_t)TQ * KW];          // x fp16 words
__device__ uint32_t  g_wqkvT[(size_t)3 * DM * KW];   // w_qkv^T fp16 words [3DM][KW]
__device__ uint32_t  g_wprojT[(size_t)DM * KW];      // w_proj^T fp16 words [DM][KW]

// ---------------------------------------------------------------------------
// helpers
// ---------------------------------------------------------------------------
__device__ __forceinline__ uint32_t packh2(float a, float b) {
    __half2 h = __floats2half2_rn(a, b);
    return *reinterpret_cast<uint32_t*>(&h);
}
__device__ __forceinline__ uint32_t h2exp2u(uint32_t x) {   // 2^x on both halves
    uint32_t r;
    asm("ex2.approx.f16x2 %0, %1;" : "=r"(r) : "r"(x));
    return r;
}

__device__ __forceinline__ void mma_f16(float* d, const uint32_t* a,
                                        uint32_t b0, uint32_t b1) {
    asm volatile(
        "mma.sync.aligned.m16n8k16.row.col.f32.f16.f16.f32 "
        "{%0,%1,%2,%3}, {%4,%5,%6,%7}, {%8,%9}, {%0,%1,%2,%3};\n"
        : "+f"(d[0]), "+f"(d[1]), "+f"(d[2]), "+f"(d[3])
        : "r"(a[0]), "r"(a[1]), "r"(a[2]), "r"(a[3]), "r"(b0), "r"(b1));
}

__device__ __forceinline__ void ldm_x4(uint32_t* r, uint32_t addr) {
    asm volatile("ldmatrix.sync.aligned.m8n8.x4.shared.b16 {%0,%1,%2,%3}, [%4];"
                 : "=r"(r[0]), "=r"(r[1]), "=r"(r[2]), "=r"(r[3]) : "r"(addr));
}
__device__ __forceinline__ void ldm_x4_t(uint32_t* r, uint32_t addr) {
    asm volatile("ldmatrix.sync.aligned.m8n8.x4.trans.shared.b16 {%0,%1,%2,%3}, [%4];"
                 : "=r"(r[0]), "=r"(r[1]), "=r"(r[2]), "=r"(r[3]) : "r"(addr));
}

__device__ __forceinline__ uint32_t s2u(const void* p) {
    uint32_t a;
    asm("{ .reg .u64 t; cvta.to.shared.u64 t, %1; cvt.u32.u64 %0, t; }"
        : "=r"(a) : "l"(p));
    return a;
}
__device__ __forceinline__ void cpa16(uint32_t dst, const void* src) {
    asm volatile("cp.async.cg.shared.global [%0], [%1], 16;\n" :: "r"(dst), "l"(src));
}
__device__ __forceinline__ void cpa_commit() {
    asm volatile("cp.async.commit_group;\n");
}
template <int N> __device__ __forceinline__ void cpa_wait() {
    asm volatile("cp.async.wait_group %0;\n" :: "n"(N));
}

// ---------------------------------------------------------------------------
// pre-processing (canonical layouts)
// ---------------------------------------------------------------------------
__global__ void cvt_h(const float* __restrict__ in, uint32_t* __restrict__ out,
                      int nwords)
{
    int i = blockIdx.x * blockDim.x + threadIdx.x;
    if (i * 4 >= nwords) return;
    const float4* p = (const float4*)(in + (size_t)i * 8);
    float4 v0 = p[0], v1 = p[1];
    uint4 w;
    w.x = packh2(v0.x, v0.y);
    w.y = packh2(v0.z, v0.w);
    w.z = packh2(v1.x, v1.y);
    w.w = packh2(v1.z, v1.w);
    *(uint4*)(out + (size_t)i * 4) = w;
}

// in [R][C] fp32 -> out [C][R/2 words] fp16x2 (canonical).
__global__ void wtrans_h(const float* __restrict__ in, uint32_t* __restrict__ out,
                         int R, int C)
{
    __shared__ float t[32][33];
    int c0 = blockIdx.x * 32, r0 = blockIdx.y * 32;
    int tx = threadIdx.x, ty = threadIdx.y;
#pragma unroll
    for (int i = 0; i < 4; i++)
        t[ty + 8 * i][tx] = in[(size_t)(r0 + ty + 8 * i) * C + c0 + tx];
    __syncthreads();
    int Rw = R / 2;
#pragma unroll
    for (int i = 0; i < 2; i++) {
        int wp = ty + 8 * i;
        out[(size_t)(c0 + tx) * Rw + r0 / 2 + wp] =
            packh2(t[2 * wp][tx], t[2 * wp + 1][tx]);
    }
}

// ---------------------------------------------------------------------------
// fp16 GEMM, ldmatrix + XOR-swizzled smem, 3-stage single-sync pipeline.
// (unchanged from round 11)
// ---------------------------------------------------------------------------
#define GOPER  (128 * 32)            // words per operand per stage
#define GSTAGE (2 * GOPER)           // words per stage (A then B)
#define QSCALE (0.125f * 1.4426950408889634f)

template <int MODE>
__global__ __launch_bounds__(256, 2)
void gemm_h(const uint32_t* __restrict__ A, const uint32_t* __restrict__ B,
            void* __restrict__ Cv, int M, int N, int Kw)
{
    __shared__ __align__(16) uint32_t sm[3 * GSTAGE];   // 96 KB
    const uint32_t s0 = s2u(sm);

    const int tid  = threadIdx.x;
    const int lane = tid & 31;
    const int warp = tid >> 5;
    const int wm   = warp & 3;
    const int wn   = warp >> 2;
    const int bx   = blockIdx.x;
    const int by   = blockIdx.y;
    const int g    = lane >> 2;
    const int tc   = lane & 3;

    const uint32_t* Ab = A + (size_t)(by * 128) * Kw;
    const uint32_t* Bb = B + (size_t)(bx * 128) * Kw;

    float acc[2][8][4];
#pragma unroll
    for (int mt = 0; mt < 2; mt++)
#pragma unroll
        for (int nt = 0; nt < 8; nt++)
#pragma unroll
            for (int j = 0; j < 4; j++) acc[mt][nt][j] = 0.f;

    auto load_stage = [&](int s, int buf) {
        uint32_t dA = s0 + (uint32_t)(buf * GSTAGE) * 4;
        uint32_t dB = dA + (uint32_t)GOPER * 4;
#pragma unroll
        for (int j = 0; j < 4; j++) {
            int idx = tid + j * 256;
            int r = idx >> 3, ch = idx & 7;
            uint32_t sw = ((uint32_t)(r * 32) + ((ch ^ (r & 7)) << 2)) * 4;  // bytes
            cpa16(dA + sw, Ab + (size_t)r * Kw + s * 32 + ch * 4);
            cpa16(dB + sw, Bb + (size_t)r * Kw + s * 32 + ch * 4);
        }
        cpa_commit();
    };

    load_stage(0, 0);
    load_stage(1, 1);

    const int arow  = wm * 32 + (lane & 15);
    const int ahi   = lane >> 4;
    const int brow  = wn * 64 + (lane & 7) + ((lane >> 4) << 3);
    const int bhi   = (lane >> 3) & 1;
    uint32_t abase  = (uint32_t)(arow * 32) * 4;
    uint32_t bbase  = (uint32_t)(brow * 32) * 4;
    uint32_t aswz[4], bswz[4];
#pragma unroll
    for (int ks = 0; ks < 4; ks++) {
        aswz[ks] = (uint32_t)(((2 * ks + ahi) ^ (arow & 7)) << 4);
        bswz[ks] = (uint32_t)(((2 * ks + bhi) ^ (brow & 7)) << 4);
    }

    const int S = Kw / 32;
    int buf = 0;
    for (int s = 0; s < S; s++) {
        if (s + 1 < S) cpa_wait<1>(); else cpa_wait<0>();
        __syncthreads();
        if (s + 2 < S) {
            int nb = buf + 2;
            if (nb >= 3) nb -= 3;
            load_stage(s + 2, nb);
        }

        const uint32_t bA = s0 + (uint32_t)(buf * GSTAGE) * 4;
        const uint32_t bB = bA + (uint32_t)GOPER * 4;

#pragma unroll
        for (int ks = 0; ks < 4; ks++) {
            uint32_t a[2][4];
            ldm_x4(a[0], bA + abase + aswz[ks]);
            ldm_x4(a[1], bA + abase + (uint32_t)(16 * 32 * 4) + aswz[ks]);
#pragma unroll
            for (int nt2 = 0; nt2 < 4; nt2++) {
                uint32_t b[4];
                ldm_x4(b, bB + bbase + (uint32_t)(nt2 * 16 * 32 * 4) + bswz[ks]);
                mma_f16(acc[0][2 * nt2],     a[0], b[0], b[1]);
                mma_f16(acc[1][2 * nt2],     a[1], b[0], b[1]);
                mma_f16(acc[0][2 * nt2 + 1], a[0], b[2], b[3]);
                mma_f16(acc[1][2 * nt2 + 1], a[1], b[2], b[3]);
            }
        }
        buf = (buf + 1 == 3) ? 0 : buf + 1;
    }

    // epilogue
#pragma unroll
    for (int mt = 0; mt < 2; mt++)
#pragma unroll
        for (int nt = 0; nt < 8; nt++) {
            int r0 = by * 128 + wm * 32 + mt * 16 + g;
            int c0 = bx * 128 + wn * 64 + nt * 8 + 2 * tc;
            float v0 = acc[mt][nt][0], v1 = acc[mt][nt][1];
            float v2 = acc[mt][nt][2], v3 = acc[mt][nt][3];
            if (MODE == 1) {
                float sc = (c0 < DM) ? QSCALE : 1.0f;   // Q: fold 1/8 and log2e
                uint32_t* C = (uint32_t*)Cv;
                int cw = c0 >> 1;
                C[(size_t)r0 * (N / 2) + cw]       = packh2(v0 * sc, v1 * sc);
                C[(size_t)(r0 + 8) * (N / 2) + cw] = packh2(v2 * sc, v3 * sc);
            } else {
                float* C = (float*)Cv;
                *(float2*)(C + (size_t)r0 * N + c0)       = make_float2(v0, v1);
                *(float2*)(C + (size_t)(r0 + 8) * N + c0) = make_float2(v2, v3);
            }
        }
}

// ---------------------------------------------------------------------------
// Causal flash attention, fp16 mma m16n8k16. 64 q-rows, 4 warps.
// Double-buffered K/V (load t+1 overlaps compute t). fp16x2 ex2 softmax +
// ones-MMA row sums. smem 45 KB static.
// ---------------------------------------------------------------------------
#define RW 36
#define KVBUF (64 * RW)             // words per K (or V) buffer
#define ONE2 0x3C003C00u            // (1.0h, 1.0h)
__global__ __launch_bounds__(128) void attn_fwd()
{
    __shared__ __align__(16) uint32_t smQ[64 * RW];
    __shared__ __align__(16) uint32_t smK[2 * KVBUF];
    __shared__ __align__(16) uint32_t smV[2 * KVBUF];
    const uint32_t bQ = s2u(smQ), bK = s2u(smK), bV = s2u(smV);

    const int tid  = threadIdx.x;
    const int lane = tid & 31;
    const int warp = tid >> 5;
    const int h    = blockIdx.y;
    const int qt   = (int)gridDim.x - 1 - (int)blockIdx.x;  // heavy tiles first
    const int q0   = qt * 64;
    const int g    = lane >> 2;
    const int tc   = lane & 3;

    auto load_kv = [&](int t, int buf) {
#pragma unroll
        for (int i = 0; i < 4; i++) {
            int idx = tid + i * 128;
            int r = idx >> 3, ch = idx & 7;
            const __half* base = g_qkv + (size_t)(t * 64 + r) * (3 * DM) + h * DH + ch * 8;
            uint32_t off = (uint32_t)(buf * KVBUF + r * RW + ch * 4) * 4;
            cpa16(bK + off, base + DM);
            cpa16(bV + off, base + 2 * DM);
        }
    };

    // ---- prologue: Q + K0/V0 in one commit group ----
#pragma unroll
    for (int i = 0; i < 4; i++) {
        int idx = tid + i * 128;
        int r = idx >> 3, ch = idx & 7;
        cpa16(bQ + (uint32_t)(r * RW + ch * 4) * 4,
              g_qkv + (size_t)(q0 + r) * (3 * DM) + h * DH + ch * 8);
    }
    load_kv(0, 0);
    cpa_commit();

    const uint32_t qoff = (uint32_t)((warp * 16 + (lane & 15)) * RW +
                                     ((lane >> 4) << 2)) * 4;
    const uint32_t koff = (uint32_t)(((lane & 7) + ((lane >> 4) << 3)) * RW +
                                     (((lane >> 3) & 1) << 2)) * 4;
    const uint32_t voff = (uint32_t)((lane & 15) * RW + ((lane >> 4) << 2)) * 4;

    float o[8][4];
#pragma unroll
    for (int nt = 0; nt < 8; nt++)
#pragma unroll
        for (int j = 0; j < 4; j++) o[nt][j] = 0.f;
    float mA = -INFINITY, mB = -INFINITY, lA = 0.f, lB = 0.f;

    for (int t = 0; t <= qt; t++) {
        __syncthreads();               // all warps done with buffer (t+1)&1
        if (t < qt) {                  // prefetch t+1 (overlaps compute t)
            load_kv(t + 1, (t + 1) & 1);
            cpa_commit();
            cpa_wait<1>();             // tile t landed, t+1 in flight
        } else {
            cpa_wait<0>();
        }
        __syncthreads();               // tile t visible to all warps

        const uint32_t kb = bK + (uint32_t)((t & 1) * KVBUF) * 4;
        const uint32_t vb = bV + (uint32_t)((t & 1) * KVBUF) * 4;

        // ---- S = Q @ K^T (log2-unit scores) ----
        float s[8][4];
#pragma unroll
        for (int nt = 0; nt < 8; nt++)
#pragma unroll
            for (int j = 0; j < 4; j++) s[nt][j] = 0.f;

#pragma unroll
        for (int kc = 0; kc < 4; kc++) {
            uint32_t a[4];
            ldm_x4(a, bQ + qoff + (uint32_t)(8 * kc) * 4);
#pragma unroll
            for (int ntp = 0; ntp < 4; ntp++) {
                uint32_t b[4];
                ldm_x4(b, kb + koff + (uint32_t)(ntp * 16 * RW + 8 * kc) * 4);
                mma_f16(s[2 * ntp],     a, b[0], b[1]);
                mma_f16(s[2 * ntp + 1], a, b[2], b[3]);
            }
        }

        // ---- causal mask on diagonal tile ----
        if (t == qt) {
            int qlA = warp * 16 + g;
            int qlB = qlA + 8;
#pragma unroll
            for (int nt = 0; nt < 8; nt++) {
                int k0 = nt * 8 + 2 * tc;
                if (k0     > qlA) s[nt][0] = -INFINITY;
                if (k0 + 1 > qlA) s[nt][1] = -INFINITY;
                if (k0     > qlB) s[nt][2] = -INFINITY;
                if (k0 + 1 > qlB) s[nt][3] = -INFINITY;
            }
        }

        // ---- row max (fp32, shuffles) ----
        float rA = -INFINITY, rB = -INFINITY;
#pragma unroll
        for (int nt = 0; nt < 8; nt++) {
            rA = fmaxf(rA, fmaxf(s[nt][0], s[nt][1]));
            rB = fmaxf(rB, fmaxf(s[nt][2], s[nt][3]));
        }
        rA = fmaxf(rA, __shfl_xor_sync(0xffffffffu, rA, 1));
        rA = fmaxf(rA, __shfl_xor_sync(0xffffffffu, rA, 2));
        rB = fmaxf(rB, __shfl_xor_sync(0xffffffffu, rB, 1));
        rB = fmaxf(rB, __shfl_xor_sync(0xffffffffu, rB, 2));

        float mAn = fmaxf(mA, rA), mBn = fmaxf(mB, rB);
        float fA = exp2f(mA - mAn), fB = exp2f(mB - mBn);

        // ---- exp in fp16x2; row sums via ones-MMA ----
        uint32_t pw[4][4];
        float dl[4] = {0.f, 0.f, 0.f, 0.f};
#pragma unroll
        for (int kc = 0; kc < 4; kc++) {
            pw[kc][0] = h2exp2u(packh2(s[2 * kc][0] - mAn,     s[2 * kc][1] - mAn));
            pw[kc][1] = h2exp2u(packh2(s[2 * kc][2] - mBn,     s[2 * kc][3] - mBn));
            pw[kc][2] = h2exp2u(packh2(s[2 * kc + 1][0] - mAn, s[2 * kc + 1][1] - mAn));
            pw[kc][3] = h2exp2u(packh2(s[2 * kc + 1][2] - mBn, s[2 * kc + 1][3] - mBn));
            mma_f16(dl, pw[kc], ONE2, ONE2);
        }

        lA = lA * fA + dl[0];
        lB = lB * fB + dl[2];
        mA = mAn; mB = mBn;
#pragma unroll
        for (int nt = 0; nt < 8; nt++) {
            o[nt][0] *= fA; o[nt][1] *= fA;
            o[nt][2] *= fB; o[nt][3] *= fB;
        }

        // ---- O += P @ V  (P = pw; V via ldmatrix.trans) ----
#pragma unroll
        for (int kc = 0; kc < 4; kc++) {
#pragma unroll
            for (int ntp = 0; ntp < 4; ntp++) {
                uint32_t b[4];
                ldm_x4_t(b, vb + voff + (uint32_t)(16 * kc * RW + ntp * 8) * 4);
                mma_f16(o[2 * ntp],     pw[kc], b[0], b[1]);
                mma_f16(o[2 * ntp + 1], pw[kc], b[2], b[3]);
            }
        }
    }

    // ---- epilogue: normalize, emit canonical fp16 words (proj-A input) ----
    float invA = 1.f / lA, invB = 1.f / lB;
    int rowA = q0 + warp * 16 + g;
#pragma unroll
    for (int nt = 0; nt < 8; nt++) {
        int hw = h * 32 + nt * 4 + tc;
        g_att[(size_t)rowA * KW + hw]       = packh2(o[nt][0] * invA, o[nt][1] * invA);
        g_att[(size_t)(rowA + 8) * KW + hw] = packh2(o[nt][2] * invB, o[nt][3] * invB);
    }
}

// ---------------------------------------------------------------------------
// Launch
// ---------------------------------------------------------------------------
extern "C" void kernel_launch(void* const* d_in, const int* in_sizes, int n_in,
                              void* d_out, int out_size)
{
    const float* x      = (const float*)d_in[0];
    const float* w_qkv  = (const float*)d_in[1];
    const float* w_proj = (const float*)d_in[2];
    float* out          = (float*)d_out;

    void *qkv_p, *att_p, *xw_p, *wqkvT_p, *wprojT_p;
    cudaGetSymbolAddress(&qkv_p,    g_qkv);
    cudaGetSymbolAddress(&att_p,    g_att);
    cudaGetSymbolAddress(&xw_p,     g_xw);
    cudaGetSymbolAddress(&wqkvT_p,  g_wqkvT);
    cudaGetSymbolAddress(&wprojT_p, g_wprojT);

    // 0) pre-process (canonical fp16)
    cvt_h<<<(TQ * KW / 4 + 255) / 256, 256>>>(x, (uint32_t*)xw_p, TQ * KW);
    wtrans_h<<<dim3(3 * DM / 32, DM / 32), dim3(32, 8)>>>(w_qkv, (uint32_t*)wqkvT_p,
                                                          DM, 3 * DM);
    wtrans_h<<<dim3(DM / 32, DM / 32), dim3(32, 8)>>>(w_proj, (uint32_t*)wprojT_p,
                                                      DM, DM);

    // 1) QKV projection (fp16 out; Q scaled by 0.125*log2e)
    gemm_h<1><<<dim3(3 * DM / 128, TQ / 128), 256>>>(
        (const uint32_t*)xw_p, (const uint32_t*)wqkvT_p, qkv_p, TQ, 3 * DM, KW);

    // 2) causal attention (64 q-rows/CTA, 4 warps, double-buffered K/V)
    attn_fwd<<<dim3(TQ / 64, NH), 128>>>();

    // 3) output projection (fp32 out)
    gemm_h<0><<<dim3(DM / 128, TQ / 128), 256>>>(
        (const uint32_t*)att_p, (const uint32_t*)wprojT_p, out, TQ, DM, KW);
}